// round 1
// baseline (speedup 1.0000x reference)
#include <cuda_runtime.h>
#include <cuda_bf16.h>
#include <cstdint>
#include <cstddef>

// Problem dims
#define Bx 4
#define Sx 1024
#define Dx 768
#define Hx 12
#define HDx 64
#define FCx 3072
#define Mx (Bx*Sx)            // 4096
#define EPSx 1e-5f
#define INV_SQRT_H 0.28867513459481287f   // 1/sqrt(12)

// ---------------- scratch (static device globals; no allocations) ----------
__device__ float g_Q   [Mx*Dx];
__device__ float g_K   [Mx*Dx];
__device__ float g_V   [Mx*Dx];
__device__ float g_alpha[(size_t)Bx*Hx*Sx*Sx];   // 201 MB
__device__ float g_att [Mx*Dx];
__device__ float g_proj[Mx*Dx];
__device__ float g_na  [Mx*Dx];
__device__ float g_lin1[Mx*FCx];
__device__ float g_lin2[Mx*Dx];

// ---------------- 128x128x8 SGEMM, 256 thr, 8x8/thread ---------------------
template<bool BIAS, bool RELU>
__global__ __launch_bounds__(256)
void sgemm128(const float* __restrict__ A, const float* __restrict__ Bm,
              const float* __restrict__ bias, float* __restrict__ C,
              int Mdim, int Ndim, int Kdim)
{
    __shared__ float As[8][128];
    __shared__ float Bs[8][128];

    const int tid  = threadIdx.x;
    const int row0 = blockIdx.y * 128;
    const int col0 = blockIdx.x * 128;

    const int la_m = tid >> 1;            // 0..127
    const int la_k = (tid & 1) * 4;       // 0 or 4
    const int lb_k = tid >> 5;            // 0..7
    const int lb_n = (tid & 31) * 4;      // 0..124

    const int ty = tid >> 4;              // 0..15
    const int tx = tid & 15;              // 0..15

    float acc[8][8];
    #pragma unroll
    for (int i = 0; i < 8; i++)
        #pragma unroll
        for (int j = 0; j < 8; j++) acc[i][j] = 0.f;

    for (int kt = 0; kt < Kdim; kt += 8) {
        float4 av = *(const float4*)&A[(size_t)(row0 + la_m) * Kdim + kt + la_k];
        As[la_k + 0][la_m] = av.x;
        As[la_k + 1][la_m] = av.y;
        As[la_k + 2][la_m] = av.z;
        As[la_k + 3][la_m] = av.w;
        float4 bv = *(const float4*)&Bm[(size_t)(kt + lb_k) * Ndim + col0 + lb_n];
        *(float4*)&Bs[lb_k][lb_n] = bv;
        __syncthreads();

        #pragma unroll
        for (int kk = 0; kk < 8; kk++) {
            float a[8], b[8];
            *(float4*)&a[0] = *(const float4*)&As[kk][ty * 8];
            *(float4*)&a[4] = *(const float4*)&As[kk][ty * 8 + 4];
            *(float4*)&b[0] = *(const float4*)&Bs[kk][tx * 8];
            *(float4*)&b[4] = *(const float4*)&Bs[kk][tx * 8 + 4];
            #pragma unroll
            for (int i = 0; i < 8; i++)
                #pragma unroll
                for (int j = 0; j < 8; j++)
                    acc[i][j] = fmaf(a[i], b[j], acc[i][j]);
        }
        __syncthreads();
    }

    float bb[8];
    if (BIAS) {
        *(float4*)&bb[0] = *(const float4*)&bias[col0 + tx * 8];
        *(float4*)&bb[4] = *(const float4*)&bias[col0 + tx * 8 + 4];
    }
    #pragma unroll
    for (int i = 0; i < 8; i++) {
        float out[8];
        #pragma unroll
        for (int j = 0; j < 8; j++) {
            float v = acc[i][j];
            if (BIAS) v += bb[j];
            if (RELU) v = fmaxf(v, 0.f);
            out[j] = v;
        }
        size_t base = (size_t)(row0 + ty * 8 + i) * Ndim + col0 + tx * 8;
        *(float4*)&C[base]     = *(float4*)&out[0];
        *(float4*)&C[base + 4] = *(float4*)&out[4];
    }
}

// ---------------- attention score: alpha = mask ? QK^T/sqrt(H) : -1e9 ------
__global__ __launch_bounds__(256)
void score_kernel(const float* __restrict__ Q, const float* __restrict__ K,
                  const int* __restrict__ mask, float* __restrict__ alpha)
{
    __shared__ float Qs[64][65];
    __shared__ float Ks[64][65];

    const int tid = threadIdx.x;
    const int bz  = blockIdx.z;           // b*H + h
    const int b   = bz / Hx;
    const int h   = bz % Hx;
    const int q0  = blockIdx.y * 64;
    const int k0  = blockIdx.x * 64;

    #pragma unroll
    for (int i = 0; i < 4; i++) {
        int f4 = tid + i * 256;            // 0..1023
        int r  = f4 >> 4;
        int c  = (f4 & 15) * 4;
        float4 qv = *(const float4*)&Q[(size_t)(b * Sx + q0 + r) * Dx + h * HDx + c];
        Qs[r][c+0] = qv.x; Qs[r][c+1] = qv.y; Qs[r][c+2] = qv.z; Qs[r][c+3] = qv.w;
        float4 kv = *(const float4*)&K[(size_t)(b * Sx + k0 + r) * Dx + h * HDx + c];
        Ks[r][c+0] = kv.x; Ks[r][c+1] = kv.y; Ks[r][c+2] = kv.z; Ks[r][c+3] = kv.w;
    }
    __syncthreads();

    const int ty = tid >> 4, tx = tid & 15;
    float acc[4][4];
    #pragma unroll
    for (int i = 0; i < 4; i++)
        #pragma unroll
        for (int j = 0; j < 4; j++) acc[i][j] = 0.f;

    #pragma unroll 8
    for (int d = 0; d < 64; d++) {
        float a[4], bb[4];
        #pragma unroll
        for (int i = 0; i < 4; i++) a[i]  = Qs[ty * 4 + i][d];
        #pragma unroll
        for (int j = 0; j < 4; j++) bb[j] = Ks[tx * 4 + j][d];
        #pragma unroll
        for (int i = 0; i < 4; i++)
            #pragma unroll
            for (int j = 0; j < 4; j++)
                acc[i][j] = fmaf(a[i], bb[j], acc[i][j]);
    }

    #pragma unroll
    for (int i = 0; i < 4; i++) {
        int q = q0 + ty * 4 + i;
        #pragma unroll
        for (int j = 0; j < 4; j++) {
            int k = k0 + tx * 4 + j;
            float v = acc[i][j] * INV_SQRT_H;
            int m = mask[(size_t)(b * Sx + q) * Sx + k];
            if (m == 0) v = -1e9f;
            alpha[((size_t)bz * Sx + q) * Sx + k] = v;
        }
    }
}

// ---------------- row softmax over 1024 ------------------------------------
__global__ __launch_bounds__(256)
void softmax_kernel(float* __restrict__ alpha)
{
    const int tid = threadIdx.x;
    const size_t base = (size_t)blockIdx.x * Sx + tid * 4;
    float4 v = *(float4*)&alpha[base];

    __shared__ float smx[8];
    __shared__ float ssum[8];

    float m = fmaxf(fmaxf(v.x, v.y), fmaxf(v.z, v.w));
    #pragma unroll
    for (int o = 16; o; o >>= 1) m = fmaxf(m, __shfl_xor_sync(0xffffffffu, m, o));
    if ((tid & 31) == 0) smx[tid >> 5] = m;
    __syncthreads();
    if (tid == 0) {
        float t = smx[0];
        #pragma unroll
        for (int w = 1; w < 8; w++) t = fmaxf(t, smx[w]);
        smx[0] = t;
    }
    __syncthreads();
    m = smx[0];

    v.x = __expf(v.x - m); v.y = __expf(v.y - m);
    v.z = __expf(v.z - m); v.w = __expf(v.w - m);
    float s = v.x + v.y + v.z + v.w;
    #pragma unroll
    for (int o = 16; o; o >>= 1) s += __shfl_xor_sync(0xffffffffu, s, o);
    if ((tid & 31) == 0) ssum[tid >> 5] = s;
    __syncthreads();
    if (tid == 0) {
        float t = 0.f;
        #pragma unroll
        for (int w = 0; w < 8; w++) t += ssum[w];
        ssum[0] = 1.f / t;
    }
    __syncthreads();
    float inv = ssum[0];
    v.x *= inv; v.y *= inv; v.z *= inv; v.w *= inv;
    *(float4*)&alpha[base] = v;
}

// ---------------- PV: att[b,q,h*64+d] = sum_k alpha * V --------------------
__global__ __launch_bounds__(256)
void pv_kernel(const float* __restrict__ alpha, const float* __restrict__ V,
               float* __restrict__ att)
{
    __shared__ float As[64][17];
    __shared__ float Vs[16][64];

    const int tid = threadIdx.x;
    const int bz  = blockIdx.z;
    const int b   = bz / Hx;
    const int h   = bz % Hx;
    const int q0  = blockIdx.x * 64;

    const int ty = tid >> 4, tx = tid & 15;

    float acc[4][4];
    #pragma unroll
    for (int i = 0; i < 4; i++)
        #pragma unroll
        for (int j = 0; j < 4; j++) acc[i][j] = 0.f;

    const int ar = tid >> 2, ac = (tid & 3) * 4;    // A tile 64x16
    const int vr = tid >> 4, vc = (tid & 15) * 4;   // V tile 16x64

    for (int kt = 0; kt < Sx; kt += 16) {
        float4 av = *(const float4*)&alpha[((size_t)bz * Sx + q0 + ar) * Sx + kt + ac];
        As[ar][ac+0] = av.x; As[ar][ac+1] = av.y; As[ar][ac+2] = av.z; As[ar][ac+3] = av.w;
        float4 vv = *(const float4*)&V[(size_t)(b * Sx + kt + vr) * Dx + h * HDx + vc];
        *(float4*)&Vs[vr][vc] = vv;
        __syncthreads();

        #pragma unroll
        for (int kk = 0; kk < 16; kk++) {
            float a[4], bb[4];
            #pragma unroll
            for (int i = 0; i < 4; i++) a[i]  = As[ty * 4 + i][kk];
            #pragma unroll
            for (int j = 0; j < 4; j++) bb[j] = Vs[kk][tx * 4 + j];
            #pragma unroll
            for (int i = 0; i < 4; i++)
                #pragma unroll
                for (int j = 0; j < 4; j++)
                    acc[i][j] = fmaf(a[i], bb[j], acc[i][j]);
        }
        __syncthreads();
    }

    #pragma unroll
    for (int i = 0; i < 4; i++)
        #pragma unroll
        for (int j = 0; j < 4; j++)
            att[(size_t)(b * Sx + q0 + ty * 4 + i) * Dx + h * HDx + tx * 4 + j] = acc[i][j];
}

// ---------------- residual add + LayerNorm over 768 ------------------------
__global__ __launch_bounds__(192)
void ln_kernel(const float* __restrict__ a, const float* __restrict__ r,
               const float* __restrict__ g, const float* __restrict__ be,
               float* __restrict__ out)
{
    const int tid = threadIdx.x;              // 0..191, 4 elems each
    const size_t base = (size_t)blockIdx.x * Dx + tid * 4;

    float4 xa = *(const float4*)&a[base];
    float4 xr = *(const float4*)&r[base];
    float x0 = xa.x + xr.x, x1 = xa.y + xr.y, x2 = xa.z + xr.z, x3 = xa.w + xr.w;

    float s = x0 + x1 + x2 + x3;
    float q = x0*x0 + x1*x1 + x2*x2 + x3*x3;
    #pragma unroll
    for (int o = 16; o; o >>= 1) {
        s += __shfl_xor_sync(0xffffffffu, s, o);
        q += __shfl_xor_sync(0xffffffffu, q, o);
    }
    __shared__ float ss[6], qq[6];
    if ((tid & 31) == 0) { ss[tid >> 5] = s; qq[tid >> 5] = q; }
    __syncthreads();
    if (tid == 0) {
        float S = 0.f, Qq = 0.f;
        #pragma unroll
        for (int w = 0; w < 6; w++) { S += ss[w]; Qq += qq[w]; }
        float mean = S * (1.f / Dx);
        float var  = Qq * (1.f / Dx) - mean * mean;
        ss[0] = mean;
        qq[0] = rsqrtf(var + EPSx);
    }
    __syncthreads();
    float mean = ss[0], rstd = qq[0];

    float4 gv = *(const float4*)&g[tid * 4];
    float4 bv = *(const float4*)&be[tid * 4];
    float4 o4;
    o4.x = (x0 - mean) * rstd * gv.x + bv.x;
    o4.y = (x1 - mean) * rstd * gv.y + bv.y;
    o4.z = (x2 - mean) * rstd * gv.z + bv.z;
    o4.w = (x3 - mean) * rstd * gv.w + bv.w;
    *(float4*)&out[base] = o4;
}

// ---------------- launch ----------------------------------------------------
extern "C" void kernel_launch(void* const* d_in, const int* in_sizes, int n_in,
                              void* d_out, int out_size)
{
    const float* x    = (const float*)d_in[0];
    const int*   mask = (const int*)  d_in[1];
    const float* WQ   = (const float*)d_in[2];
    const float* WK   = (const float*)d_in[3];
    const float* WV   = (const float*)d_in[4];
    const float* Wfc  = (const float*)d_in[5];
    const float* W1   = (const float*)d_in[6];
    const float* b1   = (const float*)d_in[7];
    const float* W2   = (const float*)d_in[8];
    const float* b2   = (const float*)d_in[9];
    const float* g1   = (const float*)d_in[10];
    const float* be1  = (const float*)d_in[11];
    const float* g2   = (const float*)d_in[12];
    const float* be2  = (const float*)d_in[13];
    float* out = (float*)d_out;

    float *Q, *K, *V, *alpha, *att, *proj, *na, *lin1, *lin2;
    cudaGetSymbolAddress((void**)&Q,     g_Q);
    cudaGetSymbolAddress((void**)&K,     g_K);
    cudaGetSymbolAddress((void**)&V,     g_V);
    cudaGetSymbolAddress((void**)&alpha, g_alpha);
    cudaGetSymbolAddress((void**)&att,   g_att);
    cudaGetSymbolAddress((void**)&proj,  g_proj);
    cudaGetSymbolAddress((void**)&na,    g_na);
    cudaGetSymbolAddress((void**)&lin1,  g_lin1);
    cudaGetSymbolAddress((void**)&lin2,  g_lin2);

    dim3 g768(Dx / 128, Mx / 128);     // (6, 32)
    dim3 gfc (FCx / 128, Mx / 128);    // (24, 32)

    // QKV projections
    sgemm128<false, false><<<g768, 256>>>(x, WQ, nullptr, Q, Mx, Dx, Dx);
    sgemm128<false, false><<<g768, 256>>>(x, WK, nullptr, K, Mx, Dx, Dx);
    sgemm128<false, false><<<g768, 256>>>(x, WV, nullptr, V, Mx, Dx, Dx);

    // attention
    score_kernel<<<dim3(Sx / 64, Sx / 64, Bx * Hx), 256>>>(Q, K, mask, alpha);
    softmax_kernel<<<Bx * Hx * Sx, 256>>>(alpha);
    pv_kernel<<<dim3(Sx / 64, 1, Bx * Hx), 256>>>(alpha, V, att);

    // output projection + LN1
    sgemm128<false, false><<<g768, 256>>>(att, Wfc, nullptr, proj, Mx, Dx, Dx);
    ln_kernel<<<Mx, 192>>>(proj, x, g1, be1, na);

    // MLP + LN2
    sgemm128<true, true ><<<gfc,  256>>>(na,   W1, b1, lin1, Mx, FCx, Dx);
    sgemm128<true, false><<<g768, 256>>>(lin1, W2, b2, lin2, Mx, Dx, FCx);
    ln_kernel<<<Mx, 192>>>(lin2, na, g2, be2, out);
}

// round 3
// speedup vs baseline: 4.4361x; 4.4361x over previous
#include <cuda_runtime.h>
#include <cuda_fp16.h>
#include <cstdint>
#include <cstddef>

// ---------------- problem dims ----------------
#define Bx 4
#define Sx 1024
#define Dx 768
#define Hx 12
#define HDx 64
#define FCx 3072
#define Mx (Bx*Sx)            // 4096
#define EPSx 1e-5f
#define INV_SQRT_H 0.28867513459481287f   // 1/sqrt(12)

// ---------------- scratch (static device globals) ----------------
__device__ __half g_xh  [Mx*Dx];
__device__ __half g_Qh  [Mx*Dx];
__device__ __half g_Kh  [Mx*Dx];
__device__ __half g_Vh  [Mx*Dx];
__device__ __half g_Vth [(size_t)Bx*Dx*Sx];        // per batch V^T [768][1024]
__device__ float  g_alpha [(size_t)Bx*Hx*Sx*Sx];   // fp32 scores (201 MB)
__device__ __half g_alphah[(size_t)Bx*Hx*Sx*Sx];   // fp16 probs  (100 MB)
__device__ __half g_atth[Mx*Dx];
__device__ float  g_proj[Mx*Dx];
__device__ float  g_na  [Mx*Dx];
__device__ __half g_nah [Mx*Dx];
__device__ __half g_lin1h[(size_t)Mx*FCx];
__device__ float  g_lin2[Mx*Dx];
__device__ __half g_WQt [Dx*Dx];
__device__ __half g_WKt [Dx*Dx];
__device__ __half g_WVt [Dx*Dx];
__device__ __half g_Wfct[Dx*Dx];
__device__ __half g_W1t [(size_t)Dx*FCx];          // [3072][768]
__device__ __half g_W2t [(size_t)Dx*FCx];          // [768][3072]

// ---------------- small helpers ----------------
__device__ __forceinline__ uint32_t smem_to_u32(const void* p) {
    uint32_t a;
    asm("{ .reg .u64 t; cvta.to.shared.u64 t, %1; cvt.u32.u64 %0, t; }" : "=r"(a) : "l"(p));
    return a;
}
__device__ __forceinline__ void cp16(uint32_t dst, const void* src) {
    asm volatile("cp.async.cg.shared.global [%0], [%1], 16;" :: "r"(dst), "l"(src));
}
#define CP_COMMIT() asm volatile("cp.async.commit_group;" ::: "memory")
template<int N> __device__ __forceinline__ void cp_wait() {
    asm volatile("cp.async.wait_group %0;" :: "n"(N) : "memory");
}
__device__ __forceinline__ void ldm_x4(uint32_t& r0, uint32_t& r1, uint32_t& r2, uint32_t& r3,
                                       uint32_t addr) {
    asm volatile("ldmatrix.sync.aligned.m8n8.x4.shared.b16 {%0,%1,%2,%3}, [%4];"
                 : "=r"(r0), "=r"(r1), "=r"(r2), "=r"(r3) : "r"(addr));
}
__device__ __forceinline__ void mma16816(float* c, const uint32_t* a, uint32_t b0, uint32_t b1) {
    asm volatile(
        "mma.sync.aligned.m16n8k16.row.col.f32.f16.f16.f32 "
        "{%0,%1,%2,%3}, {%4,%5,%6,%7}, {%8,%9}, {%0,%1,%2,%3};"
        : "+f"(c[0]), "+f"(c[1]), "+f"(c[2]), "+f"(c[3])
        : "r"(a[0]), "r"(a[1]), "r"(a[2]), "r"(a[3]), "r"(b0), "r"(b1));
}

// ---------------- fp16 tensor-core GEMM: C[M,N] = A[M,K] * Bt[N,K]^T --------
// EPI: 0 fp32 plain | 1 fp16 plain | 2 fp32 +bias | 3 fp16 +bias+relu
//      4 score (fp32, mask+scale, z-batched) | 5 PV (fp16, z-batched)
static constexpr int STAGES = 3;
static constexpr int PITCH  = 80;      // bytes per 32-half smem row (conflict-free)

template<int NT, int EPI>
__global__ __launch_bounds__(256)
void hgemm(const __half* __restrict__ A0, const __half* __restrict__ B0,
           const void* __restrict__ X, void* __restrict__ C0,
           int Kdim, int lda, int ldb, int ldc)
{
    constexpr int NTILES = NT / 16;            // n8-tiles per warp
    constexpr int ABYTES = 128 * PITCH;
    constexpr int BBYTES = NT * PITCH;
    constexpr int STB    = ABYTES + BBYTES;

    extern __shared__ __align__(128) char smem[];
    const uint32_t sb = smem_to_u32(smem);

    const int tid   = threadIdx.x;
    const int wid   = tid >> 5;
    const int lane  = tid & 31;
    const int warpM = wid & 3;                 // 0..3
    const int warpN = wid >> 2;                // 0..1

    const int m0 = blockIdx.y * 128;
    const int n0 = blockIdx.x * NT;

    const __half* A  = A0;
    const __half* Bm = B0;
    const int* mask  = nullptr;

    if (EPI == 4) {
        int z = blockIdx.z, b = z / Hx, h = z - b * Hx;
        A    = A0 + ((size_t)b * Sx) * Dx + h * HDx;
        Bm   = B0 + ((size_t)b * Sx) * Dx + h * HDx;
        mask = (const int*)X + (size_t)b * Sx * Sx;
    } else if (EPI == 5) {
        int z = blockIdx.z, b = z / Hx, h = z - b * Hx;
        A  = A0 + (size_t)z * Sx * Sx;
        Bm = B0 + ((size_t)b * Dx + h * HDx) * Sx;
    }

    float acc[2][NTILES][4];
    #pragma unroll
    for (int i = 0; i < 2; i++)
        #pragma unroll
        for (int j = 0; j < NTILES; j++)
            #pragma unroll
            for (int k = 0; k < 4; k++) acc[i][j][k] = 0.f;

    // per-thread ldmatrix offsets
    const int aRowOff = warpM * 32 + (lane & 7) + ((lane >> 3) & 1) * 8;
    const int aKOff   = (lane >> 4) * 8;                       // halves
    const int bRowOff = warpN * (NT / 2) + ((lane >> 4) & 1) * 8 + (lane & 7);
    const int bKOff   = ((lane >> 3) & 1) * 8;                 // halves

    const int nch = Kdim >> 5;

    auto load_tiles = [&](int c, int s) {
        uint32_t baseA = sb + s * STB;
        uint32_t baseB = baseA + ABYTES;
        int k0 = c * 32;
        #pragma unroll
        for (int i = 0; i < 2; i++) {                 // A: 128 rows x 4 chunks
            int idx = tid + i * 256;
            int rr = idx >> 2, q = idx & 3;
            cp16(baseA + rr * PITCH + q * 16,
                 A + (size_t)(m0 + rr) * lda + k0 + q * 8);
        }
        #pragma unroll
        for (int i = 0; i < NT / 64; i++) {           // B: NT rows x 4 chunks
            int idx = tid + i * 256;
            int rr = idx >> 2, q = idx & 3;
            cp16(baseB + rr * PITCH + q * 16,
                 Bm + (size_t)(n0 + rr) * ldb + k0 + q * 8);
        }
    };

    int pre = nch < STAGES ? nch : STAGES;
    for (int c = 0; c < pre; c++) { load_tiles(c, c); CP_COMMIT(); }

    for (int c = 0; c < nch; c++) {
        int s = c % STAGES;
        int rem = nch - 1 - c;
        if      (rem >= STAGES - 1) cp_wait<STAGES - 1>();
        else if (rem == 1)          cp_wait<1>();
        else                        cp_wait<0>();
        __syncthreads();

        uint32_t stA = sb + s * STB;
        uint32_t stB = stA + ABYTES;

        #pragma unroll
        for (int ks = 0; ks < 2; ks++) {
            uint32_t a[2][4];
            #pragma unroll
            for (int mt = 0; mt < 2; mt++)
                ldm_x4(a[mt][0], a[mt][1], a[mt][2], a[mt][3],
                       stA + (aRowOff + mt * 16) * PITCH + (ks * 16 + aKOff) * 2);
            #pragma unroll
            for (int ntp = 0; ntp < NTILES / 2; ntp++) {
                uint32_t b0, b1, b2, b3;
                ldm_x4(b0, b1, b2, b3,
                       stB + (bRowOff + ntp * 16) * PITCH + (ks * 16 + bKOff) * 2);
                #pragma unroll
                for (int mt = 0; mt < 2; mt++) {
                    mma16816(acc[mt][ntp * 2 + 0], a[mt], b0, b1);
                    mma16816(acc[mt][ntp * 2 + 1], a[mt], b2, b3);
                }
            }
        }
        __syncthreads();

        int cn = c + STAGES;
        if (cn < nch) { load_tiles(cn, s); CP_COMMIT(); }
    }

    // ---------------- epilogue ----------------
    const int rbase0 = m0 + warpM * 32 + (lane >> 2);
    const int cbase  = n0 + warpN * (NT / 2) + (lane & 3) * 2;

    #pragma unroll
    for (int mt = 0; mt < 2; mt++) {
        #pragma unroll
        for (int nt = 0; nt < NTILES; nt++) {
            int col = cbase + nt * 8;
            #pragma unroll
            for (int hf = 0; hf < 2; hf++) {
                int row = rbase0 + mt * 16 + hf * 8;
                float v0 = acc[mt][nt][hf * 2 + 0];
                float v1 = acc[mt][nt][hf * 2 + 1];
                if (EPI == 4) {
                    int z = blockIdx.z;
                    float* C = (float*)C0 + (size_t)z * Sx * Sx;
                    int2 mv = *(const int2*)&mask[(size_t)row * Sx + col];
                    float2 o;
                    o.x = mv.x ? v0 * INV_SQRT_H : -1e9f;
                    o.y = mv.y ? v1 * INV_SQRT_H : -1e9f;
                    *(float2*)&C[(size_t)row * ldc + col] = o;
                } else if (EPI == 5) {
                    int z = blockIdx.z, b = z / Hx, h = z - b * Hx;
                    __half* C = (__half*)C0 + ((size_t)b * Sx) * Dx + h * HDx;
                    *(__half2*)&C[(size_t)row * ldc + col] = __floats2half2_rn(v0, v1);
                } else if (EPI == 0) {
                    float* C = (float*)C0;
                    *(float2*)&C[(size_t)row * ldc + col] = make_float2(v0, v1);
                } else if (EPI == 1) {
                    __half* C = (__half*)C0;
                    *(__half2*)&C[(size_t)row * ldc + col] = __floats2half2_rn(v0, v1);
                } else if (EPI == 2) {
                    const float* bias = (const float*)X;
                    float* C = (float*)C0;
                    *(float2*)&C[(size_t)row * ldc + col] =
                        make_float2(v0 + bias[col], v1 + bias[col + 1]);
                } else { // EPI == 3
                    const float* bias = (const float*)X;
                    __half* C = (__half*)C0;
                    float o0 = fmaxf(v0 + bias[col], 0.f);
                    float o1 = fmaxf(v1 + bias[col + 1], 0.f);
                    *(__half2*)&C[(size_t)row * ldc + col] = __floats2half2_rn(o0, o1);
                }
            }
        }
    }
}

// ---------------- transpose(+convert): in[R][C] -> out[C][R], batched z -----
template<typename Ti, typename To>
__global__ __launch_bounds__(256)
void tconv(const Ti* __restrict__ in, To* __restrict__ out, int R, int C)
{
    __shared__ float t[32][33];
    const Ti* ip = in  + (size_t)blockIdx.z * R * C;
    To*       op = out + (size_t)blockIdx.z * R * C;
    int x  = blockIdx.x * 32 + threadIdx.x;
    int y0 = blockIdx.y * 32;
    #pragma unroll
    for (int i = threadIdx.y; i < 32; i += 8)
        t[i][threadIdx.x] = (float)ip[(size_t)(y0 + i) * C + x];
    __syncthreads();
    int ox  = y0 + threadIdx.x;
    int oy0 = blockIdx.x * 32;
    #pragma unroll
    for (int i = threadIdx.y; i < 32; i += 8)
        op[(size_t)(oy0 + i) * R + ox] = (To)t[threadIdx.x][i];
}

// ---------------- fp32 -> fp16 elementwise ---------------------------------
__global__ __launch_bounds__(256)
void conv_h(const float* __restrict__ in, __half* __restrict__ out, int n2)
{
    int i = blockIdx.x * 256 + threadIdx.x;
    if (i < n2) {
        float2 v = *(const float2*)&in[i * 2];
        *(__half2*)&out[i * 2] = __floats2half2_rn(v.x, v.y);
    }
}

// ---------------- row softmax over 1024: fp32 in, fp16 out ------------------
__global__ __launch_bounds__(256)
void softmax_kernel(const float* __restrict__ alpha, __half* __restrict__ out)
{
    const int tid = threadIdx.x;
    const size_t base = (size_t)blockIdx.x * Sx + tid * 4;
    float4 v = *(const float4*)&alpha[base];

    __shared__ float smx[8];
    __shared__ float ssum[8];

    float m = fmaxf(fmaxf(v.x, v.y), fmaxf(v.z, v.w));
    #pragma unroll
    for (int o = 16; o; o >>= 1) m = fmaxf(m, __shfl_xor_sync(0xffffffffu, m, o));
    if ((tid & 31) == 0) smx[tid >> 5] = m;
    __syncthreads();
    if (tid == 0) {
        float t = smx[0];
        #pragma unroll
        for (int w = 1; w < 8; w++) t = fmaxf(t, smx[w]);
        smx[0] = t;
    }
    __syncthreads();
    m = smx[0];

    v.x = __expf(v.x - m); v.y = __expf(v.y - m);
    v.z = __expf(v.z - m); v.w = __expf(v.w - m);
    float s = v.x + v.y + v.z + v.w;
    #pragma unroll
    for (int o = 16; o; o >>= 1) s += __shfl_xor_sync(0xffffffffu, s, o);
    if ((tid & 31) == 0) ssum[tid >> 5] = s;
    __syncthreads();
    if (tid == 0) {
        float t = 0.f;
        #pragma unroll
        for (int w = 0; w < 8; w++) t += ssum[w];
        ssum[0] = 1.f / t;
    }
    __syncthreads();
    float inv = ssum[0];
    *(__half2*)&out[base]     = __floats2half2_rn(v.x * inv, v.y * inv);
    *(__half2*)&out[base + 2] = __floats2half2_rn(v.z * inv, v.w * inv);
}

// ---------------- residual add + LayerNorm over 768 -------------------------
template<bool WH>
__global__ __launch_bounds__(192)
void ln_kernel(const float* __restrict__ a, const float* __restrict__ r,
               const float* __restrict__ g, const float* __restrict__ be,
               float* __restrict__ out, __half* __restrict__ outh)
{
    const int tid = threadIdx.x;
    const size_t base = (size_t)blockIdx.x * Dx + tid * 4;

    float4 xa = *(const float4*)&a[base];
    float4 xr = *(const float4*)&r[base];
    float x0 = xa.x + xr.x, x1 = xa.y + xr.y, x2 = xa.z + xr.z, x3 = xa.w + xr.w;

    float s = x0 + x1 + x2 + x3;
    float q = x0*x0 + x1*x1 + x2*x2 + x3*x3;
    #pragma unroll
    for (int o = 16; o; o >>= 1) {
        s += __shfl_xor_sync(0xffffffffu, s, o);
        q += __shfl_xor_sync(0xffffffffu, q, o);
    }
    __shared__ float ss[6], qq[6];
    if ((tid & 31) == 0) { ss[tid >> 5] = s; qq[tid >> 5] = q; }
    __syncthreads();
    if (tid == 0) {
        float S = 0.f, Qq = 0.f;
        #pragma unroll
        for (int w = 0; w < 6; w++) { S += ss[w]; Qq += qq[w]; }
        float mean = S * (1.f / Dx);
        float var  = Qq * (1.f / Dx) - mean * mean;
        ss[0] = mean;
        qq[0] = rsqrtf(var + EPSx);
    }
    __syncthreads();
    float mean = ss[0], rstd = qq[0];

    float4 gv = *(const float4*)&g[tid * 4];
    float4 bv = *(const float4*)&be[tid * 4];
    float4 o4;
    o4.x = (x0 - mean) * rstd * gv.x + bv.x;
    o4.y = (x1 - mean) * rstd * gv.y + bv.y;
    o4.z = (x2 - mean) * rstd * gv.z + bv.z;
    o4.w = (x3 - mean) * rstd * gv.w + bv.w;
    *(float4*)&out[base] = o4;
    if (WH) {
        *(__half2*)&outh[base]     = __floats2half2_rn(o4.x, o4.y);
        *(__half2*)&outh[base + 2] = __floats2half2_rn(o4.z, o4.w);
    }
}

// ---------------- launch ----------------------------------------------------
extern "C" void kernel_launch(void* const* d_in, const int* in_sizes, int n_in,
                              void* d_out, int out_size)
{
    const float* x    = (const float*)d_in[0];
    const int*   mask = (const int*)  d_in[1];
    const float* WQ   = (const float*)d_in[2];
    const float* WK   = (const float*)d_in[3];
    const float* WV   = (const float*)d_in[4];
    const float* Wfc  = (const float*)d_in[5];
    const float* W1   = (const float*)d_in[6];
    const float* b1   = (const float*)d_in[7];
    const float* W2   = (const float*)d_in[8];
    const float* b2   = (const float*)d_in[9];
    const float* g1   = (const float*)d_in[10];
    const float* be1  = (const float*)d_in[11];
    const float* g2   = (const float*)d_in[12];
    const float* be2  = (const float*)d_in[13];
    float* out = (float*)d_out;

    __half *xh, *Qh, *Kh, *Vh, *Vth, *alphah, *atth, *nah, *lin1h;
    __half *WQt, *WKt, *WVt, *Wfct, *W1t, *W2t;
    float *alpha, *proj, *na, *lin2;
    cudaGetSymbolAddress((void**)&xh,     g_xh);
    cudaGetSymbolAddress((void**)&Qh,     g_Qh);
    cudaGetSymbolAddress((void**)&Kh,     g_Kh);
    cudaGetSymbolAddress((void**)&Vh,     g_Vh);
    cudaGetSymbolAddress((void**)&Vth,    g_Vth);
    cudaGetSymbolAddress((void**)&alpha,  g_alpha);
    cudaGetSymbolAddress((void**)&alphah, g_alphah);
    cudaGetSymbolAddress((void**)&atth,   g_atth);
    cudaGetSymbolAddress((void**)&proj,   g_proj);
    cudaGetSymbolAddress((void**)&na,     g_na);
    cudaGetSymbolAddress((void**)&nah,    g_nah);
    cudaGetSymbolAddress((void**)&lin1h,  g_lin1h);
    cudaGetSymbolAddress((void**)&lin2,   g_lin2);
    cudaGetSymbolAddress((void**)&WQt,    g_WQt);
    cudaGetSymbolAddress((void**)&WKt,    g_WKt);
    cudaGetSymbolAddress((void**)&WVt,    g_WVt);
    cudaGetSymbolAddress((void**)&Wfct,   g_Wfct);
    cudaGetSymbolAddress((void**)&W1t,    g_W1t);
    cudaGetSymbolAddress((void**)&W2t,    g_W2t);

    constexpr int SM128 = STAGES * (128 + 128) * PITCH;   // 61440
    constexpr int SM64  = STAGES * (128 +  64) * PITCH;   // 46080
    cudaFuncSetAttribute(hgemm<128,0>, cudaFuncAttributeMaxDynamicSharedMemorySize, SM128);
    cudaFuncSetAttribute(hgemm<128,1>, cudaFuncAttributeMaxDynamicSharedMemorySize, SM128);
    cudaFuncSetAttribute(hgemm<128,2>, cudaFuncAttributeMaxDynamicSharedMemorySize, SM128);
    cudaFuncSetAttribute(hgemm<128,3>, cudaFuncAttributeMaxDynamicSharedMemorySize, SM128);
    cudaFuncSetAttribute(hgemm<128,4>, cudaFuncAttributeMaxDynamicSharedMemorySize, SM128);
    cudaFuncSetAttribute(hgemm<64,5>,  cudaFuncAttributeMaxDynamicSharedMemorySize, SM64);

    dim3 tb(32, 8);

    // input + weight conversions
    conv_h<<<(Mx*Dx/2 + 255)/256, 256>>>(x, xh, Mx*Dx/2);
    tconv<float,__half><<<dim3(Dx/32,  Dx/32, 1), tb>>>(WQ,  WQt,  Dx, Dx);
    tconv<float,__half><<<dim3(Dx/32,  Dx/32, 1), tb>>>(WK,  WKt,  Dx, Dx);
    tconv<float,__half><<<dim3(Dx/32,  Dx/32, 1), tb>>>(WV,  WVt,  Dx, Dx);
    tconv<float,__half><<<dim3(Dx/32,  Dx/32, 1), tb>>>(Wfc, Wfct, Dx, Dx);
    tconv<float,__half><<<dim3(FCx/32, Dx/32, 1), tb>>>(W1,  W1t,  Dx, FCx);
    tconv<float,__half><<<dim3(Dx/32, FCx/32, 1), tb>>>(W2,  W2t,  FCx, Dx);

    // QKV projections (M=4096, N=768, K=768) -> fp16
    hgemm<128,1><<<dim3(Dx/128, Mx/128), 256, SM128>>>(xh, WQt, nullptr, Qh, Dx, Dx, Dx, Dx);
    hgemm<128,1><<<dim3(Dx/128, Mx/128), 256, SM128>>>(xh, WKt, nullptr, Kh, Dx, Dx, Dx, Dx);
    hgemm<128,1><<<dim3(Dx/128, Mx/128), 256, SM128>>>(xh, WVt, nullptr, Vh, Dx, Dx, Dx, Dx);

    // scores: per (b,h) Q[1024,64] K^T, mask+scale -> fp32 alpha
    hgemm<128,4><<<dim3(Sx/128, Sx/128, Bx*Hx), 256, SM128>>>(Qh, Kh, mask, alpha, HDx, Dx, Dx, Sx);

    // softmax -> fp16 probs
    softmax_kernel<<<Bx*Hx*Sx, 256>>>(alpha, alphah);

    // V^T per batch, PV -> fp16 att
    tconv<__half,__half><<<dim3(Dx/32, Sx/32, Bx), tb>>>(Vh, Vth, Sx, Dx);
    hgemm<64,5><<<dim3(1, Sx/128, Bx*Hx), 256, SM64>>>(alphah, Vth, nullptr, atth, Sx, Sx, Sx, Dx);

    // output projection (fp32) + LN1 (fp32 + fp16)
    hgemm<128,0><<<dim3(Dx/128, Mx/128), 256, SM128>>>(atth, Wfct, nullptr, proj, Dx, Dx, Dx, Dx);
    ln_kernel<true><<<Mx, 192>>>(proj, x, g1, be1, na, nah);

    // MLP + LN2
    hgemm<128,3><<<dim3(FCx/128, Mx/128), 256, SM128>>>(nah,   W1t, b1, lin1h, Dx,  Dx,  Dx,  FCx);
    hgemm<128,2><<<dim3(Dx/128,  Mx/128), 256, SM128>>>(lin1h, W2t, b2, lin2,  FCx, FCx, FCx, Dx);
    ln_kernel<false><<<Mx, 192>>>(lin2, na, g2, be2, out, nullptr);
}

// round 4
// speedup vs baseline: 5.5941x; 1.2610x over previous
#include <cuda_runtime.h>
#include <cuda_fp16.h>
#include <cstdint>
#include <cstddef>

// ---------------- problem dims ----------------
#define Bx 4
#define Sx 1024
#define Dx 768
#define Hx 12
#define HDx 64
#define FCx 3072
#define Mx (Bx*Sx)            // 4096
#define EPSx 1e-5f
#define INV_SQRT_H 0.28867513459481287f   // 1/sqrt(12)

// ---------------- scratch (static device globals) ----------------
__device__ __half   g_xh  [Mx*Dx];
__device__ __half   g_Qh  [Mx*Dx];       // pre-scaled by 1/sqrt(H)
__device__ __half   g_Kh  [Mx*Dx];
__device__ __half   g_Vh  [Mx*Dx];
__device__ uint32_t g_mpk [(size_t)Mx*32];   // packed mask bits
__device__ __half   g_atth[Mx*Dx];
__device__ float    g_proj[Mx*Dx];
__device__ float    g_na  [Mx*Dx];
__device__ __half   g_nah [Mx*Dx];
__device__ __half   g_lin1h[(size_t)Mx*FCx];
__device__ float    g_lin2[Mx*Dx];
__device__ __half   g_WQt [Dx*Dx];
__device__ __half   g_WKt [Dx*Dx];
__device__ __half   g_WVt [Dx*Dx];
__device__ __half   g_Wfct[Dx*Dx];
__device__ __half   g_W1t [(size_t)Dx*FCx];
__device__ __half   g_W2t [(size_t)Dx*FCx];

// ---------------- small helpers ----------------
__device__ __forceinline__ uint32_t smem_to_u32(const void* p) {
    uint32_t a;
    asm("{ .reg .u64 t; cvta.to.shared.u64 t, %1; cvt.u32.u64 %0, t; }" : "=r"(a) : "l"(p));
    return a;
}
__device__ __forceinline__ void cp16(uint32_t dst, const void* src) {
    asm volatile("cp.async.cg.shared.global [%0], [%1], 16;" :: "r"(dst), "l"(src));
}
#define CP_COMMIT() asm volatile("cp.async.commit_group;" ::: "memory")
template<int N> __device__ __forceinline__ void cp_wait() {
    asm volatile("cp.async.wait_group %0;" :: "n"(N) : "memory");
}
__device__ __forceinline__ void ldm_x4(uint32_t& r0, uint32_t& r1, uint32_t& r2, uint32_t& r3,
                                       uint32_t addr) {
    asm volatile("ldmatrix.sync.aligned.m8n8.x4.shared.b16 {%0,%1,%2,%3}, [%4];"
                 : "=r"(r0), "=r"(r1), "=r"(r2), "=r"(r3) : "r"(addr));
}
__device__ __forceinline__ void ldm_x4_t(uint32_t& r0, uint32_t& r1, uint32_t& r2, uint32_t& r3,
                                         uint32_t addr) {
    asm volatile("ldmatrix.sync.aligned.m8n8.x4.trans.shared.b16 {%0,%1,%2,%3}, [%4];"
                 : "=r"(r0), "=r"(r1), "=r"(r2), "=r"(r3) : "r"(addr));
}
__device__ __forceinline__ void mma16816(float* c, const uint32_t* a, uint32_t b0, uint32_t b1) {
    asm volatile(
        "mma.sync.aligned.m16n8k16.row.col.f32.f16.f16.f32 "
        "{%0,%1,%2,%3}, {%4,%5,%6,%7}, {%8,%9}, {%0,%1,%2,%3};"
        : "+f"(c[0]), "+f"(c[1]), "+f"(c[2]), "+f"(c[3])
        : "r"(a[0]), "r"(a[1]), "r"(a[2]), "r"(a[3]), "r"(b0), "r"(b1));
}
__device__ __forceinline__ uint32_t h2u(float a, float b) {
    __half2 h = __floats2half2_rn(a, b);
    return *(uint32_t*)&h;
}

// ---------------- fp16 tensor-core GEMM: C[M,N] = A[M,K] * Bt[N,K]^T --------
// EPI: 0 fp32 | 1 fp16 | 2 fp32+bias | 3 fp16+bias+relu | 6 fp16 scaled
static constexpr int STAGES = 3;
static constexpr int PITCH  = 80;      // bytes per 32-half smem row

template<int NT, int EPI>
__global__ __launch_bounds__(256)
void hgemm(const __half* __restrict__ A0, const __half* __restrict__ B0,
           const void* __restrict__ X, void* __restrict__ C0,
           int Kdim, int lda, int ldb, int ldc)
{
    constexpr int NTILES = NT / 16;
    constexpr int ABYTES = 128 * PITCH;
    constexpr int BBYTES = NT * PITCH;
    constexpr int STB    = ABYTES + BBYTES;

    extern __shared__ __align__(128) char smem[];
    const uint32_t sb = smem_to_u32(smem);

    const int tid   = threadIdx.x;
    const int wid   = tid >> 5;
    const int lane  = tid & 31;
    const int warpM = wid & 3;
    const int warpN = wid >> 2;

    const int m0 = blockIdx.y * 128;
    const int n0 = blockIdx.x * NT;

    const __half* A  = A0;
    const __half* Bm = B0;

    float acc[2][NTILES][4];
    #pragma unroll
    for (int i = 0; i < 2; i++)
        #pragma unroll
        for (int j = 0; j < NTILES; j++)
            #pragma unroll
            for (int k = 0; k < 4; k++) acc[i][j][k] = 0.f;

    const int aRowOff = warpM * 32 + (lane & 7) + ((lane >> 3) & 1) * 8;
    const int aKOff   = (lane >> 4) * 8;
    const int bRowOff = warpN * (NT / 2) + ((lane >> 4) & 1) * 8 + (lane & 7);
    const int bKOff   = ((lane >> 3) & 1) * 8;

    const int nch = Kdim >> 5;

    auto load_tiles = [&](int c, int s) {
        uint32_t baseA = sb + s * STB;
        uint32_t baseB = baseA + ABYTES;
        int k0 = c * 32;
        #pragma unroll
        for (int i = 0; i < 2; i++) {
            int idx = tid + i * 256;
            int rr = idx >> 2, q = idx & 3;
            cp16(baseA + rr * PITCH + q * 16,
                 A + (size_t)(m0 + rr) * lda + k0 + q * 8);
        }
        #pragma unroll
        for (int i = 0; i < NT / 64; i++) {
            int idx = tid + i * 256;
            int rr = idx >> 2, q = idx & 3;
            cp16(baseB + rr * PITCH + q * 16,
                 Bm + (size_t)(n0 + rr) * ldb + k0 + q * 8);
        }
    };

    int pre = nch < STAGES ? nch : STAGES;
    for (int c = 0; c < pre; c++) { load_tiles(c, c); CP_COMMIT(); }

    for (int c = 0; c < nch; c++) {
        int s = c % STAGES;
        int rem = nch - 1 - c;
        if      (rem >= STAGES - 1) cp_wait<STAGES - 1>();
        else if (rem == 1)          cp_wait<1>();
        else                        cp_wait<0>();
        __syncthreads();

        uint32_t stA = sb + s * STB;
        uint32_t stB = stA + ABYTES;

        #pragma unroll
        for (int ks = 0; ks < 2; ks++) {
            uint32_t a[2][4];
            #pragma unroll
            for (int mt = 0; mt < 2; mt++)
                ldm_x4(a[mt][0], a[mt][1], a[mt][2], a[mt][3],
                       stA + (aRowOff + mt * 16) * PITCH + (ks * 16 + aKOff) * 2);
            #pragma unroll
            for (int ntp = 0; ntp < NTILES / 2; ntp++) {
                uint32_t b0, b1, b2, b3;
                ldm_x4(b0, b1, b2, b3,
                       stB + (bRowOff + ntp * 16) * PITCH + (ks * 16 + bKOff) * 2);
                #pragma unroll
                for (int mt = 0; mt < 2; mt++) {
                    mma16816(acc[mt][ntp * 2 + 0], a[mt], b0, b1);
                    mma16816(acc[mt][ntp * 2 + 1], a[mt], b2, b3);
                }
            }
        }
        __syncthreads();

        int cn = c + STAGES;
        if (cn < nch) { load_tiles(cn, s); CP_COMMIT(); }
    }

    const int rbase0 = m0 + warpM * 32 + (lane >> 2);
    const int cbase  = n0 + warpN * (NT / 2) + (lane & 3) * 2;

    #pragma unroll
    for (int mt = 0; mt < 2; mt++) {
        #pragma unroll
        for (int nt = 0; nt < NTILES; nt++) {
            int col = cbase + nt * 8;
            #pragma unroll
            for (int hf = 0; hf < 2; hf++) {
                int row = rbase0 + mt * 16 + hf * 8;
                float v0 = acc[mt][nt][hf * 2 + 0];
                float v1 = acc[mt][nt][hf * 2 + 1];
                if (EPI == 0) {
                    float* C = (float*)C0;
                    *(float2*)&C[(size_t)row * ldc + col] = make_float2(v0, v1);
                } else if (EPI == 1) {
                    __half* C = (__half*)C0;
                    *(uint32_t*)&C[(size_t)row * ldc + col] = h2u(v0, v1);
                } else if (EPI == 6) {
                    __half* C = (__half*)C0;
                    *(uint32_t*)&C[(size_t)row * ldc + col] =
                        h2u(v0 * INV_SQRT_H, v1 * INV_SQRT_H);
                } else if (EPI == 2) {
                    const float* bias = (const float*)X;
                    float* C = (float*)C0;
                    *(float2*)&C[(size_t)row * ldc + col] =
                        make_float2(v0 + bias[col], v1 + bias[col + 1]);
                } else { // EPI == 3
                    const float* bias = (const float*)X;
                    __half* C = (__half*)C0;
                    float o0 = fmaxf(v0 + bias[col], 0.f);
                    float o1 = fmaxf(v1 + bias[col + 1], 0.f);
                    *(uint32_t*)&C[(size_t)row * ldc + col] = h2u(o0, o1);
                }
            }
        }
    }
}

// ---------------- flash attention: fused QK^T/mask/softmax/PV ---------------
// Q pre-scaled. Tiles: q 128 rows (8 warps x 16), k/v 64 rows, double-buffered.
static constexpr int FPIT  = 144;    // bytes per 64-half row (conflict-free ldmatrix)
static constexpr int QBY   = 128 * FPIT;
static constexpr int TBY   = 64 * FPIT;
static constexpr int FSMEM = QBY + 4 * TBY;  // Q + 2xK + 2xV = 55296

__global__ __launch_bounds__(256, 2)
void flash_kernel(const __half* __restrict__ Qg, const __half* __restrict__ Kg,
                  const __half* __restrict__ Vg, const uint32_t* __restrict__ mpk,
                  __half* __restrict__ Og)
{
    extern __shared__ __align__(128) char smem[];
    const uint32_t sQ = smem_to_u32(smem);
    const uint32_t sK = sQ + QBY;
    const uint32_t sV = sK + 2 * TBY;

    const int tid = threadIdx.x, wid = tid >> 5, lane = tid & 31;
    const int q0 = blockIdx.x * 128;
    const int z = blockIdx.y, b = z / Hx, h = z - b * Hx;

    const __half* Qp = Qg + ((size_t)b * Sx + q0) * Dx + h * HDx;
    const __half* Kp = Kg + ((size_t)b * Sx) * Dx + h * HDx;
    const __half* Vp = Vg + ((size_t)b * Sx) * Dx + h * HDx;
    const uint32_t* mp = mpk + ((size_t)b * Sx + q0) * 32;

    // Q tile load (once)
    #pragma unroll
    for (int i = 0; i < 4; i++) {
        int idx = tid + i * 256;
        int r = idx >> 3, c = idx & 7;
        cp16(sQ + r * FPIT + c * 16, Qp + (size_t)r * Dx + c * 8);
    }
    auto loadKV = [&](int t, int s) {
        const __half* kb = Kp + (size_t)t * 64 * Dx;
        const __half* vb = Vp + (size_t)t * 64 * Dx;
        #pragma unroll
        for (int i = 0; i < 2; i++) {
            int idx = tid + i * 256;
            int r = idx >> 3, c = idx & 7;
            cp16(sK + s * TBY + r * FPIT + c * 16, kb + (size_t)r * Dx + c * 8);
            cp16(sV + s * TBY + r * FPIT + c * 16, vb + (size_t)r * Dx + c * 8);
        }
    };
    loadKV(0, 0); CP_COMMIT();
    loadKV(1, 1); CP_COMMIT();

    const int r  = lane >> 2;     // 0..7
    const int cq = lane & 3;      // 0..3
    const int rowL  = wid * 16 + r;        // local q rows rowL, rowL+8

    float acc_o[8][4];
    #pragma unroll
    for (int i = 0; i < 8; i++)
        #pragma unroll
        for (int j = 0; j < 4; j++) acc_o[i][j] = 0.f;
    float m0r = -1e30f, m1r = -1e30f, l0 = 0.f, l1 = 0.f;

    // precomputed ldmatrix intra-warp offsets
    const uint32_t qAddrBase = sQ + (wid * 16 + (lane & 15)) * FPIT + (lane >> 4) * 16;
    const int kRow = (lane & 7) + ((lane >> 4) & 1) * 8;
    const int kColB = ((lane >> 3) & 1) * 16;
    const int vRow = (lane & 7) + ((lane >> 3) & 1) * 8;
    const int vColB = ((lane >> 4) & 1) * 16;

    for (int t = 0; t < 16; t++) {
        cp_wait<1>();
        __syncthreads();
        int s = t & 1;
        uint32_t stK = sK + s * TBY, stV = sV + s * TBY;

        // ---- S = Q K^T (128x64 tile; this warp: 16x64) ----
        float sc[8][4];
        #pragma unroll
        for (int i = 0; i < 8; i++)
            #pragma unroll
            for (int j = 0; j < 4; j++) sc[i][j] = 0.f;

        #pragma unroll
        for (int j = 0; j < 4; j++) {            // k16 over head dim
            uint32_t qf[4];
            ldm_x4(qf[0], qf[1], qf[2], qf[3], qAddrBase + j * 32);
            #pragma unroll
            for (int np = 0; np < 4; np++) {     // 16 kv cols per step
                uint32_t b0, b1, b2, b3;
                ldm_x4(b0, b1, b2, b3,
                       stK + (np * 16 + kRow) * FPIT + j * 32 + kColB);
                mma16816(sc[np * 2 + 0], qf, b0, b1);
                mma16816(sc[np * 2 + 1], qf, b2, b3);
            }
        }

        // ---- mask ----
        const uint32_t mw0 = mp[(size_t)rowL * 32 + t * 2];
        const uint32_t mw1 = mp[(size_t)rowL * 32 + t * 2 + 1];
        const uint32_t nw0 = mp[(size_t)(rowL + 8) * 32 + t * 2];
        const uint32_t nw1 = mp[(size_t)(rowL + 8) * 32 + t * 2 + 1];
        #pragma unroll
        for (int nt = 0; nt < 8; nt++) {
            int colb = nt * 8 + 2 * cq;
            uint32_t wr  = (colb < 32) ? mw0 : mw1;
            uint32_t wr8 = (colb < 32) ? nw0 : nw1;
            int sh = colb & 31;
            sc[nt][0] = ((wr  >> sh)       & 1) ? sc[nt][0] : -1e9f;
            sc[nt][1] = ((wr  >> (sh + 1)) & 1) ? sc[nt][1] : -1e9f;
            sc[nt][2] = ((wr8 >> sh)       & 1) ? sc[nt][2] : -1e9f;
            sc[nt][3] = ((wr8 >> (sh + 1)) & 1) ? sc[nt][3] : -1e9f;
        }

        // ---- online softmax ----
        float mx0 = -1e30f, mx1 = -1e30f;
        #pragma unroll
        for (int nt = 0; nt < 8; nt++) {
            mx0 = fmaxf(mx0, fmaxf(sc[nt][0], sc[nt][1]));
            mx1 = fmaxf(mx1, fmaxf(sc[nt][2], sc[nt][3]));
        }
        mx0 = fmaxf(mx0, __shfl_xor_sync(0xffffffffu, mx0, 1));
        mx0 = fmaxf(mx0, __shfl_xor_sync(0xffffffffu, mx0, 2));
        mx1 = fmaxf(mx1, __shfl_xor_sync(0xffffffffu, mx1, 1));
        mx1 = fmaxf(mx1, __shfl_xor_sync(0xffffffffu, mx1, 2));

        float mn0 = fmaxf(m0r, mx0), mn1 = fmaxf(m1r, mx1);
        float f0 = __expf(m0r - mn0), f1 = __expf(m1r - mn1);
        m0r = mn0; m1r = mn1;

        float s0 = 0.f, s1 = 0.f;
        #pragma unroll
        for (int nt = 0; nt < 8; nt++) {
            sc[nt][0] = __expf(sc[nt][0] - mn0);
            sc[nt][1] = __expf(sc[nt][1] - mn0);
            sc[nt][2] = __expf(sc[nt][2] - mn1);
            sc[nt][3] = __expf(sc[nt][3] - mn1);
            s0 += sc[nt][0] + sc[nt][1];
            s1 += sc[nt][2] + sc[nt][3];
        }
        s0 += __shfl_xor_sync(0xffffffffu, s0, 1);
        s0 += __shfl_xor_sync(0xffffffffu, s0, 2);
        s1 += __shfl_xor_sync(0xffffffffu, s1, 1);
        s1 += __shfl_xor_sync(0xffffffffu, s1, 2);
        l0 = l0 * f0 + s0;
        l1 = l1 * f1 + s1;

        #pragma unroll
        for (int nt = 0; nt < 8; nt++) {
            acc_o[nt][0] *= f0; acc_o[nt][1] *= f0;
            acc_o[nt][2] *= f1; acc_o[nt][3] *= f1;
        }

        // ---- P (fp16 frags) x V ----
        uint32_t ph[4][4];
        #pragma unroll
        for (int j = 0; j < 4; j++) {
            ph[j][0] = h2u(sc[2*j  ][0], sc[2*j  ][1]);
            ph[j][1] = h2u(sc[2*j  ][2], sc[2*j  ][3]);
            ph[j][2] = h2u(sc[2*j+1][0], sc[2*j+1][1]);
            ph[j][3] = h2u(sc[2*j+1][2], sc[2*j+1][3]);
        }
        #pragma unroll
        for (int j = 0; j < 4; j++) {          // k16 over kv
            #pragma unroll
            for (int nn = 0; nn < 4; nn++) {   // 16 d-cols per step
                uint32_t b0, b1, b2, b3;
                ldm_x4_t(b0, b1, b2, b3,
                         stV + (j * 16 + vRow) * FPIT + nn * 32 + vColB);
                mma16816(acc_o[nn * 2 + 0], ph[j], b0, b1);
                mma16816(acc_o[nn * 2 + 1], ph[j], b2, b3);
            }
        }

        __syncthreads();
        if (t + 2 < 16) loadKV(t + 2, s);
        CP_COMMIT();
    }

    // ---- epilogue ----
    float i0 = 1.f / l0, i1 = 1.f / l1;
    __half* Op = Og + ((size_t)b * Sx + q0 + wid * 16) * Dx + h * HDx;
    #pragma unroll
    for (int nt = 0; nt < 8; nt++) {
        int col = nt * 8 + 2 * cq;
        *(uint32_t*)&Op[(size_t)r * Dx + col] =
            h2u(acc_o[nt][0] * i0, acc_o[nt][1] * i0);
        *(uint32_t*)&Op[(size_t)(r + 8) * Dx + col] =
            h2u(acc_o[nt][2] * i1, acc_o[nt][3] * i1);
    }
}

// ---------------- mask bit-packing: int32 [4096][1024] -> uint32 [4096][32] -
__global__ __launch_bounds__(256)
void pack_mask(const int* __restrict__ mask, uint32_t* __restrict__ pk)
{
    int warp = blockIdx.x * 8 + (threadIdx.x >> 5);
    int lane = threadIdx.x & 31;
    const int* rowp = mask + (size_t)warp * 1024;
    uint32_t*  outp = pk   + (size_t)warp * 32;
    #pragma unroll
    for (int w = 0; w < 32; w++) {
        int v = rowp[w * 32 + lane];
        uint32_t word = __ballot_sync(0xffffffffu, v != 0);
        if (lane == 0) outp[w] = word;
    }
}

// ---------------- transpose(+convert): in[R][C] -> out[C][R] ---------------
template<typename Ti, typename To>
__global__ __launch_bounds__(256)
void tconv(const Ti* __restrict__ in, To* __restrict__ out, int R, int C)
{
    __shared__ float t[32][33];
    int x  = blockIdx.x * 32 + threadIdx.x;
    int y0 = blockIdx.y * 32;
    #pragma unroll
    for (int i = threadIdx.y; i < 32; i += 8)
        t[i][threadIdx.x] = (float)in[(size_t)(y0 + i) * C + x];
    __syncthreads();
    int ox  = y0 + threadIdx.x;
    int oy0 = blockIdx.x * 32;
    #pragma unroll
    for (int i = threadIdx.y; i < 32; i += 8)
        out[(size_t)(oy0 + i) * R + ox] = (To)t[threadIdx.x][i];
}

// ---------------- fp32 -> fp16 elementwise ----------------------------------
__global__ __launch_bounds__(256)
void conv_h(const float* __restrict__ in, __half* __restrict__ out, int n2)
{
    int i = blockIdx.x * 256 + threadIdx.x;
    if (i < n2) {
        float2 v = *(const float2*)&in[i * 2];
        *(uint32_t*)&out[i * 2] = h2u(v.x, v.y);
    }
}

// ---------------- residual add + LayerNorm over 768 -------------------------
template<bool WH>
__global__ __launch_bounds__(192)
void ln_kernel(const float* __restrict__ a, const float* __restrict__ r,
               const float* __restrict__ g, const float* __restrict__ be,
               float* __restrict__ out, __half* __restrict__ outh)
{
    const int tid = threadIdx.x;
    const size_t base = (size_t)blockIdx.x * Dx + tid * 4;

    float4 xa = *(const float4*)&a[base];
    float4 xr = *(const float4*)&r[base];
    float x0 = xa.x + xr.x, x1 = xa.y + xr.y, x2 = xa.z + xr.z, x3 = xa.w + xr.w;

    float s = x0 + x1 + x2 + x3;
    float q = x0*x0 + x1*x1 + x2*x2 + x3*x3;
    #pragma unroll
    for (int o = 16; o; o >>= 1) {
        s += __shfl_xor_sync(0xffffffffu, s, o);
        q += __shfl_xor_sync(0xffffffffu, q, o);
    }
    __shared__ float ss[6], qq[6];
    if ((tid & 31) == 0) { ss[tid >> 5] = s; qq[tid >> 5] = q; }
    __syncthreads();
    if (tid == 0) {
        float S = 0.f, Qq = 0.f;
        #pragma unroll
        for (int w = 0; w < 6; w++) { S += ss[w]; Qq += qq[w]; }
        float mean = S * (1.f / Dx);
        float var  = Qq * (1.f / Dx) - mean * mean;
        ss[0] = mean;
        qq[0] = rsqrtf(var + EPSx);
    }
    __syncthreads();
    float mean = ss[0], rstd = qq[0];

    float4 gv = *(const float4*)&g[tid * 4];
    float4 bv = *(const float4*)&be[tid * 4];
    float4 o4;
    o4.x = (x0 - mean) * rstd * gv.x + bv.x;
    o4.y = (x1 - mean) * rstd * gv.y + bv.y;
    o4.z = (x2 - mean) * rstd * gv.z + bv.z;
    o4.w = (x3 - mean) * rstd * gv.w + bv.w;
    *(float4*)&out[base] = o4;
    if (WH) {
        *(uint32_t*)&outh[base]     = h2u(o4.x, o4.y);
        *(uint32_t*)&outh[base + 2] = h2u(o4.z, o4.w);
    }
}

// ---------------- launch ----------------------------------------------------
extern "C" void kernel_launch(void* const* d_in, const int* in_sizes, int n_in,
                              void* d_out, int out_size)
{
    const float* x    = (const float*)d_in[0];
    const int*   mask = (const int*)  d_in[1];
    const float* WQ   = (const float*)d_in[2];
    const float* WK   = (const float*)d_in[3];
    const float* WV   = (const float*)d_in[4];
    const float* Wfc  = (const float*)d_in[5];
    const float* W1   = (const float*)d_in[6];
    const float* b1   = (const float*)d_in[7];
    const float* W2   = (const float*)d_in[8];
    const float* b2   = (const float*)d_in[9];
    const float* g1   = (const float*)d_in[10];
    const float* be1  = (const float*)d_in[11];
    const float* g2   = (const float*)d_in[12];
    const float* be2  = (const float*)d_in[13];
    float* out = (float*)d_out;

    __half *xh, *Qh, *Kh, *Vh, *atth, *nah, *lin1h;
    __half *WQt, *WKt, *WVt, *Wfct, *W1t, *W2t;
    float *proj, *na, *lin2;
    uint32_t* mpk;
    cudaGetSymbolAddress((void**)&xh,     g_xh);
    cudaGetSymbolAddress((void**)&Qh,     g_Qh);
    cudaGetSymbolAddress((void**)&Kh,     g_Kh);
    cudaGetSymbolAddress((void**)&Vh,     g_Vh);
    cudaGetSymbolAddress((void**)&mpk,    g_mpk);
    cudaGetSymbolAddress((void**)&atth,   g_atth);
    cudaGetSymbolAddress((void**)&proj,   g_proj);
    cudaGetSymbolAddress((void**)&na,     g_na);
    cudaGetSymbolAddress((void**)&nah,    g_nah);
    cudaGetSymbolAddress((void**)&lin1h,  g_lin1h);
    cudaGetSymbolAddress((void**)&lin2,   g_lin2);
    cudaGetSymbolAddress((void**)&WQt,    g_WQt);
    cudaGetSymbolAddress((void**)&WKt,    g_WKt);
    cudaGetSymbolAddress((void**)&WVt,    g_WVt);
    cudaGetSymbolAddress((void**)&Wfct,   g_Wfct);
    cudaGetSymbolAddress((void**)&W1t,    g_W1t);
    cudaGetSymbolAddress((void**)&W2t,    g_W2t);

    constexpr int SM128 = STAGES * (128 + 128) * PITCH;   // 61440
    cudaFuncSetAttribute(hgemm<128,0>, cudaFuncAttributeMaxDynamicSharedMemorySize, SM128);
    cudaFuncSetAttribute(hgemm<128,1>, cudaFuncAttributeMaxDynamicSharedMemorySize, SM128);
    cudaFuncSetAttribute(hgemm<128,2>, cudaFuncAttributeMaxDynamicSharedMemorySize, SM128);
    cudaFuncSetAttribute(hgemm<128,3>, cudaFuncAttributeMaxDynamicSharedMemorySize, SM128);
    cudaFuncSetAttribute(hgemm<128,6>, cudaFuncAttributeMaxDynamicSharedMemorySize, SM128);
    cudaFuncSetAttribute(flash_kernel, cudaFuncAttributeMaxDynamicSharedMemorySize, FSMEM);

    dim3 tb(32, 8);

    // conversions + mask packing
    conv_h<<<(Mx*Dx/2 + 255)/256, 256>>>(x, xh, Mx*Dx/2);
    pack_mask<<<Mx/8, 256>>>(mask, mpk);
    tconv<float,__half><<<dim3(Dx/32,  Dx/32),  tb>>>(WQ,  WQt,  Dx, Dx);
    tconv<float,__half><<<dim3(Dx/32,  Dx/32),  tb>>>(WK,  WKt,  Dx, Dx);
    tconv<float,__half><<<dim3(Dx/32,  Dx/32),  tb>>>(WV,  WVt,  Dx, Dx);
    tconv<float,__half><<<dim3(Dx/32,  Dx/32),  tb>>>(Wfc, Wfct, Dx, Dx);
    tconv<float,__half><<<dim3(FCx/32, Dx/32),  tb>>>(W1,  W1t,  Dx, FCx);
    tconv<float,__half><<<dim3(Dx/32,  FCx/32), tb>>>(W2,  W2t,  FCx, Dx);

    // QKV projections (Q pre-scaled by 1/sqrt(H))
    hgemm<128,6><<<dim3(Dx/128, Mx/128), 256, SM128>>>(xh, WQt, nullptr, Qh, Dx, Dx, Dx, Dx);
    hgemm<128,1><<<dim3(Dx/128, Mx/128), 256, SM128>>>(xh, WKt, nullptr, Kh, Dx, Dx, Dx, Dx);
    hgemm<128,1><<<dim3(Dx/128, Mx/128), 256, SM128>>>(xh, WVt, nullptr, Vh, Dx, Dx, Dx, Dx);

    // fused attention
    flash_kernel<<<dim3(Sx/128, Bx*Hx), 256, FSMEM>>>(Qh, Kh, Vh, mpk, atth);

    // output projection + LN1
    hgemm<128,0><<<dim3(Dx/128, Mx/128), 256, SM128>>>(atth, Wfct, nullptr, proj, Dx, Dx, Dx, Dx);
    ln_kernel<true><<<Mx, 192>>>(proj, x, g1, be1, na, nah);

    // MLP + LN2
    hgemm<128,3><<<dim3(FCx/128, Mx/128), 256, SM128>>>(nah,   W1t, b1, lin1h, Dx,  Dx,  Dx,  FCx);
    hgemm<128,2><<<dim3(Dx/128,  Mx/128), 256, SM128>>>(lin1h, W2t, b2, lin2,  FCx, FCx, FCx, Dx);
    ln_kernel<false><<<Mx, 192>>>(lin2, na, g2, be2, out, nullptr);
}

// round 5
// speedup vs baseline: 6.5001x; 1.1620x over previous
#include <cuda_runtime.h>
#include <cuda_fp16.h>
#include <cstdint>
#include <cstddef>

// ---------------- problem dims ----------------
#define Bx 4
#define Sx 1024
#define Dx 768
#define Hx 12
#define HDx 64
#define FCx 3072
#define Mx (Bx*Sx)            // 4096
#define EPSx 1e-5f
#define INV_SQRT_H 0.28867513459481287f   // 1/sqrt(12)

// ---------------- scratch (static device globals) ----------------
__device__ __half   g_xh  [Mx*Dx];
__device__ __half   g_QKVh[(size_t)3*Mx*Dx];     // Q (pre-scaled) | K | V
__device__ uint32_t g_mpk [(size_t)Mx*32];       // packed mask bits
__device__ __half   g_atth[Mx*Dx];
__device__ float    g_proj[Mx*Dx];
__device__ float    g_na  [Mx*Dx];
__device__ __half   g_nah [Mx*Dx];
__device__ __half   g_lin1h[(size_t)Mx*FCx];
__device__ float    g_lin2[Mx*Dx];
__device__ __half   g_Wqkvt[(size_t)3*Dx*Dx];    // [2304][768]
__device__ __half   g_Wfct[Dx*Dx];
__device__ __half   g_W1t [(size_t)Dx*FCx];
__device__ __half   g_W2t [(size_t)Dx*FCx];

// ---------------- small helpers ----------------
__device__ __forceinline__ uint32_t smem_to_u32(const void* p) {
    uint32_t a;
    asm("{ .reg .u64 t; cvta.to.shared.u64 t, %1; cvt.u32.u64 %0, t; }" : "=r"(a) : "l"(p));
    return a;
}
__device__ __forceinline__ void cp16(uint32_t dst, const void* src) {
    asm volatile("cp.async.cg.shared.global [%0], [%1], 16;" :: "r"(dst), "l"(src));
}
#define CP_COMMIT() asm volatile("cp.async.commit_group;" ::: "memory")
template<int N> __device__ __forceinline__ void cp_wait() {
    asm volatile("cp.async.wait_group %0;" :: "n"(N) : "memory");
}
__device__ __forceinline__ void ldm_x4(uint32_t& r0, uint32_t& r1, uint32_t& r2, uint32_t& r3,
                                       uint32_t addr) {
    asm volatile("ldmatrix.sync.aligned.m8n8.x4.shared.b16 {%0,%1,%2,%3}, [%4];"
                 : "=r"(r0), "=r"(r1), "=r"(r2), "=r"(r3) : "r"(addr));
}
__device__ __forceinline__ void ldm_x4_t(uint32_t& r0, uint32_t& r1, uint32_t& r2, uint32_t& r3,
                                         uint32_t addr) {
    asm volatile("ldmatrix.sync.aligned.m8n8.x4.trans.shared.b16 {%0,%1,%2,%3}, [%4];"
                 : "=r"(r0), "=r"(r1), "=r"(r2), "=r"(r3) : "r"(addr));
}
__device__ __forceinline__ void mma16816(float* c, const uint32_t* a, uint32_t b0, uint32_t b1) {
    asm volatile(
        "mma.sync.aligned.m16n8k16.row.col.f32.f16.f16.f32 "
        "{%0,%1,%2,%3}, {%4,%5,%6,%7}, {%8,%9}, {%0,%1,%2,%3};"
        : "+f"(c[0]), "+f"(c[1]), "+f"(c[2]), "+f"(c[3])
        : "r"(a[0]), "r"(a[1]), "r"(a[2]), "r"(a[3]), "r"(b0), "r"(b1));
}
__device__ __forceinline__ uint32_t h2u(float a, float b) {
    __half2 h = __floats2half2_rn(a, b);
    return *(uint32_t*)&h;
}

// ---------------- fp16 tensor-core GEMM: C[M,N] = A[M,K] * Bt[N,K]^T --------
// EPI: 0 fp32 | 2 fp32+bias | 3 fp16+bias+relu | 7 fused-QKV routing
static constexpr int STAGES = 4;
static constexpr int PITCH  = 80;      // bytes per 32-half smem row

template<int NT, int EPI>
__global__ __launch_bounds__(256)
void hgemm(const __half* __restrict__ A, const __half* __restrict__ Bm,
           const void* __restrict__ X, void* __restrict__ C0,
           int Kdim, int lda, int ldb, int ldc)
{
    constexpr int NTILES = NT / 16;
    constexpr int ABYTES = 128 * PITCH;
    constexpr int BBYTES = NT * PITCH;
    constexpr int STB    = ABYTES + BBYTES;

    extern __shared__ __align__(128) char smem[];
    const uint32_t sb = smem_to_u32(smem);

    const int tid   = threadIdx.x;
    const int wid   = tid >> 5;
    const int lane  = tid & 31;
    const int warpM = wid & 3;
    const int warpN = wid >> 2;

    const int m0 = blockIdx.y * 128;
    const int n0 = blockIdx.x * NT;

    float acc[2][NTILES][4];
    #pragma unroll
    for (int i = 0; i < 2; i++)
        #pragma unroll
        for (int j = 0; j < NTILES; j++)
            #pragma unroll
            for (int k = 0; k < 4; k++) acc[i][j][k] = 0.f;

    const int aRowOff = warpM * 32 + (lane & 7) + ((lane >> 3) & 1) * 8;
    const int aKOff   = (lane >> 4) * 8;
    const int bRowOff = warpN * (NT / 2) + ((lane >> 4) & 1) * 8 + (lane & 7);
    const int bKOff   = ((lane >> 3) & 1) * 8;

    const int nch = Kdim >> 5;

    auto load_tiles = [&](int c, int s) {
        uint32_t baseA = sb + s * STB;
        uint32_t baseB = baseA + ABYTES;
        int k0 = c * 32;
        #pragma unroll
        for (int i = 0; i < 2; i++) {
            int idx = tid + i * 256;
            int rr = idx >> 2, q = idx & 3;
            cp16(baseA + rr * PITCH + q * 16,
                 A + (size_t)(m0 + rr) * lda + k0 + q * 8);
        }
        #pragma unroll
        for (int i = 0; i < NT / 64; i++) {
            int idx = tid + i * 256;
            int rr = idx >> 2, q = idx & 3;
            cp16(baseB + rr * PITCH + q * 16,
                 Bm + (size_t)(n0 + rr) * ldb + k0 + q * 8);
        }
    };

    // prologue: S-1 stages in flight
    #pragma unroll
    for (int c = 0; c < STAGES - 1; c++) { load_tiles(c, c); CP_COMMIT(); }

    for (int c = 0; c < nch; c++) {
        cp_wait<STAGES - 2>();        // oldest pending group (chunk c) complete
        __syncthreads();              // single barrier per iteration

        int s = c % STAGES;
        uint32_t stA = sb + s * STB;
        uint32_t stB = stA + ABYTES;

        #pragma unroll
        for (int ks = 0; ks < 2; ks++) {
            uint32_t a[2][4];
            #pragma unroll
            for (int mt = 0; mt < 2; mt++)
                ldm_x4(a[mt][0], a[mt][1], a[mt][2], a[mt][3],
                       stA + (aRowOff + mt * 16) * PITCH + (ks * 16 + aKOff) * 2);
            #pragma unroll
            for (int ntp = 0; ntp < NTILES / 2; ntp++) {
                uint32_t b0, b1, b2, b3;
                ldm_x4(b0, b1, b2, b3,
                       stB + (bRowOff + ntp * 16) * PITCH + (ks * 16 + bKOff) * 2);
                #pragma unroll
                for (int mt = 0; mt < 2; mt++) {
                    mma16816(acc[mt][ntp * 2 + 0], a[mt], b0, b1);
                    mma16816(acc[mt][ntp * 2 + 1], a[mt], b2, b3);
                }
            }
        }

        // refill stage (c-1)%S with chunk c+S-1 (freed at iter c-1, safe after top sync)
        int cn = c + STAGES - 1;
        if (cn < nch) load_tiles(cn, cn % STAGES);
        CP_COMMIT();                  // commit (possibly empty) to keep group count
    }

    const int rbase0 = m0 + warpM * 32 + (lane >> 2);
    const int cbase  = n0 + warpN * (NT / 2) + (lane & 3) * 2;

    #pragma unroll
    for (int mt = 0; mt < 2; mt++) {
        #pragma unroll
        for (int nt = 0; nt < NTILES; nt++) {
            int col = cbase + nt * 8;
            #pragma unroll
            for (int hf = 0; hf < 2; hf++) {
                int row = rbase0 + mt * 16 + hf * 8;
                float v0 = acc[mt][nt][hf * 2 + 0];
                float v1 = acc[mt][nt][hf * 2 + 1];
                if (EPI == 0) {
                    float* C = (float*)C0;
                    *(float2*)&C[(size_t)row * ldc + col] = make_float2(v0, v1);
                } else if (EPI == 7) {
                    __half* C = (__half*)C0;
                    int seg = (col >= 2 * Dx) ? 2 : (col >= Dx ? 1 : 0);
                    int cc  = col - seg * Dx;
                    float scl = (seg == 0) ? INV_SQRT_H : 1.f;
                    *(uint32_t*)&C[(size_t)seg * Mx * Dx + (size_t)row * Dx + cc] =
                        h2u(v0 * scl, v1 * scl);
                } else if (EPI == 2) {
                    const float* bias = (const float*)X;
                    float* C = (float*)C0;
                    *(float2*)&C[(size_t)row * ldc + col] =
                        make_float2(v0 + bias[col], v1 + bias[col + 1]);
                } else { // EPI == 3
                    const float* bias = (const float*)X;
                    __half* C = (__half*)C0;
                    float o0 = fmaxf(v0 + bias[col], 0.f);
                    float o1 = fmaxf(v1 + bias[col + 1], 0.f);
                    *(uint32_t*)&C[(size_t)row * ldc + col] = h2u(o0, o1);
                }
            }
        }
    }
}

// ---------------- flash attention: fused QK^T/mask/softmax/PV ---------------
static constexpr int FPIT  = 144;    // bytes per 64-half row
static constexpr int QBY   = 128 * FPIT;
static constexpr int TBY   = 64 * FPIT;
static constexpr int FSMEM = QBY + 4 * TBY;

__global__ __launch_bounds__(256, 2)
void flash_kernel(const __half* __restrict__ Qg, const __half* __restrict__ Kg,
                  const __half* __restrict__ Vg, const uint32_t* __restrict__ mpk,
                  __half* __restrict__ Og)
{
    extern __shared__ __align__(128) char smem[];
    const uint32_t sQ = smem_to_u32(smem);
    const uint32_t sK = sQ + QBY;
    const uint32_t sV = sK + 2 * TBY;

    const int tid = threadIdx.x, wid = tid >> 5, lane = tid & 31;
    const int q0 = blockIdx.x * 128;
    const int z = blockIdx.y, b = z / Hx, h = z - b * Hx;

    const __half* Qp = Qg + ((size_t)b * Sx + q0) * Dx + h * HDx;
    const __half* Kp = Kg + ((size_t)b * Sx) * Dx + h * HDx;
    const __half* Vp = Vg + ((size_t)b * Sx) * Dx + h * HDx;
    const uint32_t* mp = mpk + ((size_t)b * Sx + q0) * 32;

    #pragma unroll
    for (int i = 0; i < 4; i++) {
        int idx = tid + i * 256;
        int r = idx >> 3, c = idx & 7;
        cp16(sQ + r * FPIT + c * 16, Qp + (size_t)r * Dx + c * 8);
    }
    auto loadKV = [&](int t, int s) {
        const __half* kb = Kp + (size_t)t * 64 * Dx;
        const __half* vb = Vp + (size_t)t * 64 * Dx;
        #pragma unroll
        for (int i = 0; i < 2; i++) {
            int idx = tid + i * 256;
            int r = idx >> 3, c = idx & 7;
            cp16(sK + s * TBY + r * FPIT + c * 16, kb + (size_t)r * Dx + c * 8);
            cp16(sV + s * TBY + r * FPIT + c * 16, vb + (size_t)r * Dx + c * 8);
        }
    };
    loadKV(0, 0); CP_COMMIT();
    loadKV(1, 1); CP_COMMIT();

    const int r  = lane >> 2;
    const int cq = lane & 3;
    const int rowL = wid * 16 + r;

    float acc_o[8][4];
    #pragma unroll
    for (int i = 0; i < 8; i++)
        #pragma unroll
        for (int j = 0; j < 4; j++) acc_o[i][j] = 0.f;
    float m0r = -1e30f, m1r = -1e30f, l0 = 0.f, l1 = 0.f;

    const uint32_t qAddrBase = sQ + (wid * 16 + (lane & 15)) * FPIT + (lane >> 4) * 16;
    const int kRow = (lane & 7) + ((lane >> 4) & 1) * 8;
    const int kColB = ((lane >> 3) & 1) * 16;
    const int vRow = (lane & 7) + ((lane >> 3) & 1) * 8;
    const int vColB = ((lane >> 4) & 1) * 16;

    for (int t = 0; t < 16; t++) {
        cp_wait<1>();
        __syncthreads();
        int s = t & 1;
        uint32_t stK = sK + s * TBY, stV = sV + s * TBY;

        float sc[8][4];
        #pragma unroll
        for (int i = 0; i < 8; i++)
            #pragma unroll
            for (int j = 0; j < 4; j++) sc[i][j] = 0.f;

        #pragma unroll
        for (int j = 0; j < 4; j++) {
            uint32_t qf[4];
            ldm_x4(qf[0], qf[1], qf[2], qf[3], qAddrBase + j * 32);
            #pragma unroll
            for (int np = 0; np < 4; np++) {
                uint32_t b0, b1, b2, b3;
                ldm_x4(b0, b1, b2, b3,
                       stK + (np * 16 + kRow) * FPIT + j * 32 + kColB);
                mma16816(sc[np * 2 + 0], qf, b0, b1);
                mma16816(sc[np * 2 + 1], qf, b2, b3);
            }
        }

        const uint32_t mw0 = mp[(size_t)rowL * 32 + t * 2];
        const uint32_t mw1 = mp[(size_t)rowL * 32 + t * 2 + 1];
        const uint32_t nw0 = mp[(size_t)(rowL + 8) * 32 + t * 2];
        const uint32_t nw1 = mp[(size_t)(rowL + 8) * 32 + t * 2 + 1];
        #pragma unroll
        for (int nt = 0; nt < 8; nt++) {
            int colb = nt * 8 + 2 * cq;
            uint32_t wr  = (colb < 32) ? mw0 : mw1;
            uint32_t wr8 = (colb < 32) ? nw0 : nw1;
            int sh = colb & 31;
            sc[nt][0] = ((wr  >> sh)       & 1) ? sc[nt][0] : -1e9f;
            sc[nt][1] = ((wr  >> (sh + 1)) & 1) ? sc[nt][1] : -1e9f;
            sc[nt][2] = ((wr8 >> sh)       & 1) ? sc[nt][2] : -1e9f;
            sc[nt][3] = ((wr8 >> (sh + 1)) & 1) ? sc[nt][3] : -1e9f;
        }

        float mx0 = -1e30f, mx1 = -1e30f;
        #pragma unroll
        for (int nt = 0; nt < 8; nt++) {
            mx0 = fmaxf(mx0, fmaxf(sc[nt][0], sc[nt][1]));
            mx1 = fmaxf(mx1, fmaxf(sc[nt][2], sc[nt][3]));
        }
        mx0 = fmaxf(mx0, __shfl_xor_sync(0xffffffffu, mx0, 1));
        mx0 = fmaxf(mx0, __shfl_xor_sync(0xffffffffu, mx0, 2));
        mx1 = fmaxf(mx1, __shfl_xor_sync(0xffffffffu, mx1, 1));
        mx1 = fmaxf(mx1, __shfl_xor_sync(0xffffffffu, mx1, 2));

        float mn0 = fmaxf(m0r, mx0), mn1 = fmaxf(m1r, mx1);
        float f0 = __expf(m0r - mn0), f1 = __expf(m1r - mn1);
        m0r = mn0; m1r = mn1;

        float s0 = 0.f, s1 = 0.f;
        #pragma unroll
        for (int nt = 0; nt < 8; nt++) {
            sc[nt][0] = __expf(sc[nt][0] - mn0);
            sc[nt][1] = __expf(sc[nt][1] - mn0);
            sc[nt][2] = __expf(sc[nt][2] - mn1);
            sc[nt][3] = __expf(sc[nt][3] - mn1);
            s0 += sc[nt][0] + sc[nt][1];
            s1 += sc[nt][2] + sc[nt][3];
        }
        s0 += __shfl_xor_sync(0xffffffffu, s0, 1);
        s0 += __shfl_xor_sync(0xffffffffu, s0, 2);
        s1 += __shfl_xor_sync(0xffffffffu, s1, 1);
        s1 += __shfl_xor_sync(0xffffffffu, s1, 2);
        l0 = l0 * f0 + s0;
        l1 = l1 * f1 + s1;

        #pragma unroll
        for (int nt = 0; nt < 8; nt++) {
            acc_o[nt][0] *= f0; acc_o[nt][1] *= f0;
            acc_o[nt][2] *= f1; acc_o[nt][3] *= f1;
        }

        uint32_t ph[4][4];
        #pragma unroll
        for (int j = 0; j < 4; j++) {
            ph[j][0] = h2u(sc[2*j  ][0], sc[2*j  ][1]);
            ph[j][1] = h2u(sc[2*j  ][2], sc[2*j  ][3]);
            ph[j][2] = h2u(sc[2*j+1][0], sc[2*j+1][1]);
            ph[j][3] = h2u(sc[2*j+1][2], sc[2*j+1][3]);
        }
        #pragma unroll
        for (int j = 0; j < 4; j++) {
            #pragma unroll
            for (int nn = 0; nn < 4; nn++) {
                uint32_t b0, b1, b2, b3;
                ldm_x4_t(b0, b1, b2, b3,
                         stV + (j * 16 + vRow) * FPIT + nn * 32 + vColB);
                mma16816(acc_o[nn * 2 + 0], ph[j], b0, b1);
                mma16816(acc_o[nn * 2 + 1], ph[j], b2, b3);
            }
        }

        __syncthreads();
        if (t + 2 < 16) loadKV(t + 2, s);
        CP_COMMIT();
    }

    float i0 = 1.f / l0, i1 = 1.f / l1;
    __half* Op = Og + ((size_t)b * Sx + q0 + wid * 16) * Dx + h * HDx;
    #pragma unroll
    for (int nt = 0; nt < 8; nt++) {
        int col = nt * 8 + 2 * cq;
        *(uint32_t*)&Op[(size_t)r * Dx + col] =
            h2u(acc_o[nt][0] * i0, acc_o[nt][1] * i0);
        *(uint32_t*)&Op[(size_t)(r + 8) * Dx + col] =
            h2u(acc_o[nt][2] * i1, acc_o[nt][3] * i1);
    }
}

// ---------------- mask bit-packing ------------------------------------------
__global__ __launch_bounds__(256)
void pack_mask(const int* __restrict__ mask, uint32_t* __restrict__ pk)
{
    int warp = blockIdx.x * 8 + (threadIdx.x >> 5);
    int lane = threadIdx.x & 31;
    const int* rowp = mask + (size_t)warp * 1024;
    uint32_t*  outp = pk   + (size_t)warp * 32;
    #pragma unroll
    for (int w = 0; w < 32; w++) {
        int v = rowp[w * 32 + lane];
        uint32_t word = __ballot_sync(0xffffffffu, v != 0);
        if (lane == 0) outp[w] = word;
    }
}

// ---------------- transpose(+convert): in[R][C] -> out[C][R] ----------------
template<typename Ti, typename To>
__global__ __launch_bounds__(256)
void tconv(const Ti* __restrict__ in, To* __restrict__ out, int R, int C)
{
    __shared__ float t[32][33];
    int x  = blockIdx.x * 32 + threadIdx.x;
    int y0 = blockIdx.y * 32;
    #pragma unroll
    for (int i = threadIdx.y; i < 32; i += 8)
        t[i][threadIdx.x] = (float)in[(size_t)(y0 + i) * C + x];
    __syncthreads();
    int ox  = y0 + threadIdx.x;
    int oy0 = blockIdx.x * 32;
    #pragma unroll
    for (int i = threadIdx.y; i < 32; i += 8)
        out[(size_t)(oy0 + i) * R + ox] = (To)t[threadIdx.x][i];
}

// ---------------- fp32 -> fp16 elementwise ----------------------------------
__global__ __launch_bounds__(256)
void conv_h(const float* __restrict__ in, __half* __restrict__ out, int n2)
{
    int i = blockIdx.x * 256 + threadIdx.x;
    if (i < n2) {
        float2 v = *(const float2*)&in[i * 2];
        *(uint32_t*)&out[i * 2] = h2u(v.x, v.y);
    }
}

// ---------------- residual add + LayerNorm over 768 -------------------------
template<bool WH>
__global__ __launch_bounds__(192)
void ln_kernel(const float* __restrict__ a, const float* __restrict__ r,
               const float* __restrict__ g, const float* __restrict__ be,
               float* __restrict__ out, __half* __restrict__ outh)
{
    const int tid = threadIdx.x;
    const size_t base = (size_t)blockIdx.x * Dx + tid * 4;

    float4 xa = *(const float4*)&a[base];
    float4 xr = *(const float4*)&r[base];
    float x0 = xa.x + xr.x, x1 = xa.y + xr.y, x2 = xa.z + xr.z, x3 = xa.w + xr.w;

    float s = x0 + x1 + x2 + x3;
    float q = x0*x0 + x1*x1 + x2*x2 + x3*x3;
    #pragma unroll
    for (int o = 16; o; o >>= 1) {
        s += __shfl_xor_sync(0xffffffffu, s, o);
        q += __shfl_xor_sync(0xffffffffu, q, o);
    }
    __shared__ float ss[6], qq[6];
    if ((tid & 31) == 0) { ss[tid >> 5] = s; qq[tid >> 5] = q; }
    __syncthreads();
    if (tid == 0) {
        float S = 0.f, Qq = 0.f;
        #pragma unroll
        for (int w = 0; w < 6; w++) { S += ss[w]; Qq += qq[w]; }
        float mean = S * (1.f / Dx);
        float var  = Qq * (1.f / Dx) - mean * mean;
        ss[0] = mean;
        qq[0] = rsqrtf(var + EPSx);
    }
    __syncthreads();
    float mean = ss[0], rstd = qq[0];

    float4 gv = *(const float4*)&g[tid * 4];
    float4 bv = *(const float4*)&be[tid * 4];
    float4 o4;
    o4.x = (x0 - mean) * rstd * gv.x + bv.x;
    o4.y = (x1 - mean) * rstd * gv.y + bv.y;
    o4.z = (x2 - mean) * rstd * gv.z + bv.z;
    o4.w = (x3 - mean) * rstd * gv.w + bv.w;
    *(float4*)&out[base] = o4;
    if (WH) {
        *(uint32_t*)&outh[base]     = h2u(o4.x, o4.y);
        *(uint32_t*)&outh[base + 2] = h2u(o4.z, o4.w);
    }
}

// ---------------- launch ----------------------------------------------------
extern "C" void kernel_launch(void* const* d_in, const int* in_sizes, int n_in,
                              void* d_out, int out_size)
{
    const float* x    = (const float*)d_in[0];
    const int*   mask = (const int*)  d_in[1];
    const float* WQ   = (const float*)d_in[2];
    const float* WK   = (const float*)d_in[3];
    const float* WV   = (const float*)d_in[4];
    const float* Wfc  = (const float*)d_in[5];
    const float* W1   = (const float*)d_in[6];
    const float* b1   = (const float*)d_in[7];
    const float* W2   = (const float*)d_in[8];
    const float* b2   = (const float*)d_in[9];
    const float* g1   = (const float*)d_in[10];
    const float* be1  = (const float*)d_in[11];
    const float* g2   = (const float*)d_in[12];
    const float* be2  = (const float*)d_in[13];
    float* out = (float*)d_out;

    __half *xh, *QKVh, *atth, *nah, *lin1h;
    __half *Wqkvt, *Wfct, *W1t, *W2t;
    float *proj, *na, *lin2;
    uint32_t* mpk;
    cudaGetSymbolAddress((void**)&xh,     g_xh);
    cudaGetSymbolAddress((void**)&QKVh,   g_QKVh);
    cudaGetSymbolAddress((void**)&mpk,    g_mpk);
    cudaGetSymbolAddress((void**)&atth,   g_atth);
    cudaGetSymbolAddress((void**)&proj,   g_proj);
    cudaGetSymbolAddress((void**)&na,     g_na);
    cudaGetSymbolAddress((void**)&nah,    g_nah);
    cudaGetSymbolAddress((void**)&lin1h,  g_lin1h);
    cudaGetSymbolAddress((void**)&lin2,   g_lin2);
    cudaGetSymbolAddress((void**)&Wqkvt,  g_Wqkvt);
    cudaGetSymbolAddress((void**)&Wfct,   g_Wfct);
    cudaGetSymbolAddress((void**)&W1t,    g_W1t);
    cudaGetSymbolAddress((void**)&W2t,    g_W2t);

    constexpr int SM128 = STAGES * (128 + 128) * PITCH;   // 81920
    cudaFuncSetAttribute(hgemm<128,0>, cudaFuncAttributeMaxDynamicSharedMemorySize, SM128);
    cudaFuncSetAttribute(hgemm<128,2>, cudaFuncAttributeMaxDynamicSharedMemorySize, SM128);
    cudaFuncSetAttribute(hgemm<128,3>, cudaFuncAttributeMaxDynamicSharedMemorySize, SM128);
    cudaFuncSetAttribute(hgemm<128,7>, cudaFuncAttributeMaxDynamicSharedMemorySize, SM128);
    cudaFuncSetAttribute(flash_kernel, cudaFuncAttributeMaxDynamicSharedMemorySize, FSMEM);

    dim3 tb(32, 8);

    // conversions + mask packing; WQ/WK/WV pack into one [2304][768] buffer
    conv_h<<<(Mx*Dx/2 + 255)/256, 256>>>(x, xh, Mx*Dx/2);
    pack_mask<<<Mx/8, 256>>>(mask, mpk);
    tconv<float,__half><<<dim3(Dx/32,  Dx/32),  tb>>>(WQ,  Wqkvt,            Dx, Dx);
    tconv<float,__half><<<dim3(Dx/32,  Dx/32),  tb>>>(WK,  Wqkvt + Dx*Dx,    Dx, Dx);
    tconv<float,__half><<<dim3(Dx/32,  Dx/32),  tb>>>(WV,  Wqkvt + 2*Dx*Dx,  Dx, Dx);
    tconv<float,__half><<<dim3(Dx/32,  Dx/32),  tb>>>(Wfc, Wfct, Dx, Dx);
    tconv<float,__half><<<dim3(FCx/32, Dx/32),  tb>>>(W1,  W1t,  Dx, FCx);
    tconv<float,__half><<<dim3(Dx/32,  FCx/32), tb>>>(W2,  W2t,  FCx, Dx);

    // fused QKV projection (M=4096, N=2304, K=768), epilogue routes Q/K/V
    hgemm<128,7><<<dim3(3*Dx/128, Mx/128), 256, SM128>>>(xh, Wqkvt, nullptr, QKVh,
                                                         Dx, Dx, Dx, Dx);

    // fused attention
    __half* Qh = QKVh;
    __half* Kh = QKVh + (size_t)Mx * Dx;
    __half* Vh = QKVh + (size_t)2 * Mx * Dx;
    flash_kernel<<<dim3(Sx/128, Bx*Hx), 256, FSMEM>>>(Qh, Kh, Vh, mpk, atth);

    // output projection + LN1
    hgemm<128,0><<<dim3(Dx/128, Mx/128), 256, SM128>>>(atth, Wfct, nullptr, proj, Dx, Dx, Dx, Dx);
    ln_kernel<true><<<Mx, 192>>>(proj, x, g1, be1, na, nah);

    // MLP + LN2
    hgemm<128,3><<<dim3(FCx/128, Mx/128), 256, SM128>>>(nah,   W1t, b1, lin1h, Dx,  Dx,  Dx,  FCx);
    hgemm<128,2><<<dim3(Dx/128,  Mx/128), 256, SM128>>>(lin1h, W2t, b2, lin2,  FCx, FCx, FCx, Dx);
    ln_kernel<false><<<Mx, 192>>>(lin2, na, g2, be2, out, nullptr);
}

// round 6
// speedup vs baseline: 6.8853x; 1.0593x over previous
#include <cuda_runtime.h>
#include <cuda_fp16.h>
#include <cstdint>
#include <cstddef>

// ---------------- problem dims ----------------
#define Bx 4
#define Sx 1024
#define Dx 768
#define Hx 12
#define HDx 64
#define FCx 3072
#define Mx (Bx*Sx)            // 4096
#define EPSx 1e-5f
#define INV_SQRT_H 0.28867513459481287f   // 1/sqrt(12)

// ---------------- scratch (static device globals) ----------------
__device__ __half   g_xh  [Mx*Dx];
__device__ __half   g_QKVh[(size_t)3*Mx*Dx];     // Q (pre-scaled) | K | V
__device__ uint32_t g_mpk [(size_t)Mx*32];       // packed mask bits
__device__ __half   g_atth[Mx*Dx];
__device__ float    g_proj[Mx*Dx];
__device__ float    g_na  [Mx*Dx];
__device__ __half   g_nah [Mx*Dx];
__device__ __half   g_lin1h[(size_t)Mx*FCx];
__device__ float    g_lin2[Mx*Dx];
__device__ __half   g_Wqkv[(size_t)Dx*3*Dx];     // [768][2304] row-major K x N
__device__ __half   g_Wfch[Dx*Dx];               // [768][768]
__device__ __half   g_W1h [(size_t)Dx*FCx];      // [768][3072]
__device__ __half   g_W2h [(size_t)FCx*Dx];      // [3072][768]

// ---------------- small helpers ----------------
__device__ __forceinline__ uint32_t smem_to_u32(const void* p) {
    uint32_t a;
    asm("{ .reg .u64 t; cvta.to.shared.u64 t, %1; cvt.u32.u64 %0, t; }" : "=r"(a) : "l"(p));
    return a;
}
__device__ __forceinline__ void cp16(uint32_t dst, const void* src) {
    asm volatile("cp.async.cg.shared.global [%0], [%1], 16;" :: "r"(dst), "l"(src));
}
#define CP_COMMIT() asm volatile("cp.async.commit_group;" ::: "memory")
template<int N> __device__ __forceinline__ void cp_wait() {
    asm volatile("cp.async.wait_group %0;" :: "n"(N) : "memory");
}
__device__ __forceinline__ void ldm_x4(uint32_t& r0, uint32_t& r1, uint32_t& r2, uint32_t& r3,
                                       uint32_t addr) {
    asm volatile("ldmatrix.sync.aligned.m8n8.x4.shared.b16 {%0,%1,%2,%3}, [%4];"
                 : "=r"(r0), "=r"(r1), "=r"(r2), "=r"(r3) : "r"(addr));
}
__device__ __forceinline__ void ldm_x4_t(uint32_t& r0, uint32_t& r1, uint32_t& r2, uint32_t& r3,
                                         uint32_t addr) {
    asm volatile("ldmatrix.sync.aligned.m8n8.x4.trans.shared.b16 {%0,%1,%2,%3}, [%4];"
                 : "=r"(r0), "=r"(r1), "=r"(r2), "=r"(r3) : "r"(addr));
}
__device__ __forceinline__ void mma16816(float* c, const uint32_t* a, uint32_t b0, uint32_t b1) {
    asm volatile(
        "mma.sync.aligned.m16n8k16.row.col.f32.f16.f16.f32 "
        "{%0,%1,%2,%3}, {%4,%5,%6,%7}, {%8,%9}, {%0,%1,%2,%3};"
        : "+f"(c[0]), "+f"(c[1]), "+f"(c[2]), "+f"(c[3])
        : "r"(a[0]), "r"(a[1]), "r"(a[2]), "r"(a[3]), "r"(b0), "r"(b1));
}
__device__ __forceinline__ uint32_t h2u(float a, float b) {
    __half2 h = __floats2half2_rn(a, b);
    return *(uint32_t*)&h;
}

// ---------------- fp16 TC GEMM: C[M,N] = A[M,K] * B[K,N] (B row-major) -----
// EPI: 0 fp32 | 2 fp32+bias | 3 fp16+bias+relu | 7 fused-QKV routing
static constexpr int STAGES = 4;
static constexpr int PITCH  = 80;                 // A: bytes per 32-half row
static constexpr int PITCHB = 272;                // B: bytes per 128-half k-row

template<int NT, int EPI>
__global__ __launch_bounds__(256)
void hgemm(const __half* __restrict__ A, const __half* __restrict__ Bm,
           const void* __restrict__ X, void* __restrict__ C0,
           int Kdim, int lda, int ldb, int ldc)
{
    constexpr int NTILES = NT / 16;
    constexpr int ABYTES = 128 * PITCH;
    constexpr int BBYTES = 32 * PITCHB;
    constexpr int STB    = ABYTES + BBYTES;

    extern __shared__ __align__(128) char smem[];
    const uint32_t sb = smem_to_u32(smem);

    const int tid   = threadIdx.x;
    const int wid   = tid >> 5;
    const int lane  = tid & 31;
    const int warpM = wid & 3;
    const int warpN = wid >> 2;

    const int m0 = blockIdx.y * 128;
    const int n0 = blockIdx.x * NT;

    float acc[2][NTILES][4];
    #pragma unroll
    for (int i = 0; i < 2; i++)
        #pragma unroll
        for (int j = 0; j < NTILES; j++)
            #pragma unroll
            for (int k = 0; k < 4; k++) acc[i][j][k] = 0.f;

    const int aRowOff = warpM * 32 + (lane & 7) + ((lane >> 3) & 1) * 8;
    const int aKOff   = (lane >> 4) * 8;
    // B (trans-ldmatrix from row-major [K][N]), pattern validated by flash PV
    const int bRow  = (lane & 7) + ((lane >> 3) & 1) * 8;
    const int bColB = ((lane >> 4) & 1) * 16;      // bytes

    const int nch = Kdim >> 5;

    auto load_tiles = [&](int c, int s) {
        uint32_t baseA = sb + s * STB;
        uint32_t baseB = baseA + ABYTES;
        int k0 = c * 32;
        #pragma unroll
        for (int i = 0; i < 2; i++) {               // A: 128 rows x 32 halves
            int idx = tid + i * 256;
            int rr = idx >> 2, q = idx & 3;
            cp16(baseA + rr * PITCH + q * 16,
                 A + (size_t)(m0 + rr) * lda + k0 + q * 8);
        }
        #pragma unroll
        for (int i = 0; i < NT / 64; i++) {         // B: 32 k-rows x NT halves
            int idx = tid + i * 256;
            int rr = idx >> 4, q = idx & 15;        // NT/8 = 16 chunks per row
            cp16(baseB + rr * PITCHB + q * 16,
                 Bm + (size_t)(k0 + rr) * ldb + n0 + q * 8);
        }
    };

    #pragma unroll
    for (int c = 0; c < STAGES - 1; c++) { load_tiles(c, c); CP_COMMIT(); }

    for (int c = 0; c < nch; c++) {
        cp_wait<STAGES - 2>();
        __syncthreads();

        int s = c % STAGES;
        uint32_t stA = sb + s * STB;
        uint32_t stB = stA + ABYTES;

        #pragma unroll
        for (int ks = 0; ks < 2; ks++) {
            uint32_t a[2][4];
            #pragma unroll
            for (int mt = 0; mt < 2; mt++)
                ldm_x4(a[mt][0], a[mt][1], a[mt][2], a[mt][3],
                       stA + (aRowOff + mt * 16) * PITCH + (ks * 16 + aKOff) * 2);
            #pragma unroll
            for (int ntp = 0; ntp < NTILES / 2; ntp++) {
                uint32_t b0, b1, b2, b3;
                ldm_x4_t(b0, b1, b2, b3,
                         stB + (ks * 16 + bRow) * PITCHB
                             + (warpN * (NT / 2) + ntp * 16) * 2 + bColB);
                #pragma unroll
                for (int mt = 0; mt < 2; mt++) {
                    mma16816(acc[mt][ntp * 2 + 0], a[mt], b0, b1);
                    mma16816(acc[mt][ntp * 2 + 1], a[mt], b2, b3);
                }
            }
        }

        int cn = c + STAGES - 1;
        if (cn < nch) load_tiles(cn, cn % STAGES);
        CP_COMMIT();
    }

    const int rbase0 = m0 + warpM * 32 + (lane >> 2);
    const int cbase  = n0 + warpN * (NT / 2) + (lane & 3) * 2;

    #pragma unroll
    for (int mt = 0; mt < 2; mt++) {
        #pragma unroll
        for (int nt = 0; nt < NTILES; nt++) {
            int col = cbase + nt * 8;
            #pragma unroll
            for (int hf = 0; hf < 2; hf++) {
                int row = rbase0 + mt * 16 + hf * 8;
                float v0 = acc[mt][nt][hf * 2 + 0];
                float v1 = acc[mt][nt][hf * 2 + 1];
                if (EPI == 0) {
                    float* C = (float*)C0;
                    *(float2*)&C[(size_t)row * ldc + col] = make_float2(v0, v1);
                } else if (EPI == 7) {
                    __half* C = (__half*)C0;
                    int seg = (col >= 2 * Dx) ? 2 : (col >= Dx ? 1 : 0);
                    int cc  = col - seg * Dx;
                    float scl = (seg == 0) ? INV_SQRT_H : 1.f;
                    *(uint32_t*)&C[(size_t)seg * Mx * Dx + (size_t)row * Dx + cc] =
                        h2u(v0 * scl, v1 * scl);
                } else if (EPI == 2) {
                    const float* bias = (const float*)X;
                    float* C = (float*)C0;
                    *(float2*)&C[(size_t)row * ldc + col] =
                        make_float2(v0 + bias[col], v1 + bias[col + 1]);
                } else { // EPI == 3
                    const float* bias = (const float*)X;
                    __half* C = (__half*)C0;
                    float o0 = fmaxf(v0 + bias[col], 0.f);
                    float o1 = fmaxf(v1 + bias[col + 1], 0.f);
                    *(uint32_t*)&C[(size_t)row * ldc + col] = h2u(o0, o1);
                }
            }
        }
    }
}

// ---------------- flash attention: fused QK^T/mask/softmax/PV ---------------
static constexpr int FPIT  = 144;
static constexpr int QBY   = 128 * FPIT;
static constexpr int TBY   = 64 * FPIT;
static constexpr int FSMEM = QBY + 4 * TBY;

__global__ __launch_bounds__(256, 2)
void flash_kernel(const __half* __restrict__ Qg, const __half* __restrict__ Kg,
                  const __half* __restrict__ Vg, const uint32_t* __restrict__ mpk,
                  __half* __restrict__ Og)
{
    extern __shared__ __align__(128) char smem[];
    const uint32_t sQ = smem_to_u32(smem);
    const uint32_t sK = sQ + QBY;
    const uint32_t sV = sK + 2 * TBY;

    const int tid = threadIdx.x, wid = tid >> 5, lane = tid & 31;
    const int q0 = blockIdx.x * 128;
    const int z = blockIdx.y, b = z / Hx, h = z - b * Hx;

    const __half* Qp = Qg + ((size_t)b * Sx + q0) * Dx + h * HDx;
    const __half* Kp = Kg + ((size_t)b * Sx) * Dx + h * HDx;
    const __half* Vp = Vg + ((size_t)b * Sx) * Dx + h * HDx;
    const uint32_t* mp = mpk + ((size_t)b * Sx + q0) * 32;

    #pragma unroll
    for (int i = 0; i < 4; i++) {
        int idx = tid + i * 256;
        int r = idx >> 3, c = idx & 7;
        cp16(sQ + r * FPIT + c * 16, Qp + (size_t)r * Dx + c * 8);
    }
    auto loadKV = [&](int t, int s) {
        const __half* kb = Kp + (size_t)t * 64 * Dx;
        const __half* vb = Vp + (size_t)t * 64 * Dx;
        #pragma unroll
        for (int i = 0; i < 2; i++) {
            int idx = tid + i * 256;
            int r = idx >> 3, c = idx & 7;
            cp16(sK + s * TBY + r * FPIT + c * 16, kb + (size_t)r * Dx + c * 8);
            cp16(sV + s * TBY + r * FPIT + c * 16, vb + (size_t)r * Dx + c * 8);
        }
    };
    loadKV(0, 0); CP_COMMIT();
    loadKV(1, 1); CP_COMMIT();

    const int r  = lane >> 2;
    const int cq = lane & 3;
    const int rowL = wid * 16 + r;

    float acc_o[8][4];
    #pragma unroll
    for (int i = 0; i < 8; i++)
        #pragma unroll
        for (int j = 0; j < 4; j++) acc_o[i][j] = 0.f;
    float m0r = -1e30f, m1r = -1e30f, l0 = 0.f, l1 = 0.f;

    const uint32_t qAddrBase = sQ + (wid * 16 + (lane & 15)) * FPIT + (lane >> 4) * 16;
    const int kRow = (lane & 7) + ((lane >> 4) & 1) * 8;
    const int kColB = ((lane >> 3) & 1) * 16;
    const int vRow = (lane & 7) + ((lane >> 3) & 1) * 8;
    const int vColB = ((lane >> 4) & 1) * 16;

    for (int t = 0; t < 16; t++) {
        cp_wait<1>();
        __syncthreads();
        int s = t & 1;
        uint32_t stK = sK + s * TBY, stV = sV + s * TBY;

        float sc[8][4];
        #pragma unroll
        for (int i = 0; i < 8; i++)
            #pragma unroll
            for (int j = 0; j < 4; j++) sc[i][j] = 0.f;

        #pragma unroll
        for (int j = 0; j < 4; j++) {
            uint32_t qf[4];
            ldm_x4(qf[0], qf[1], qf[2], qf[3], qAddrBase + j * 32);
            #pragma unroll
            for (int np = 0; np < 4; np++) {
                uint32_t b0, b1, b2, b3;
                ldm_x4(b0, b1, b2, b3,
                       stK + (np * 16 + kRow) * FPIT + j * 32 + kColB);
                mma16816(sc[np * 2 + 0], qf, b0, b1);
                mma16816(sc[np * 2 + 1], qf, b2, b3);
            }
        }

        const uint32_t mw0 = mp[(size_t)rowL * 32 + t * 2];
        const uint32_t mw1 = mp[(size_t)rowL * 32 + t * 2 + 1];
        const uint32_t nw0 = mp[(size_t)(rowL + 8) * 32 + t * 2];
        const uint32_t nw1 = mp[(size_t)(rowL + 8) * 32 + t * 2 + 1];
        #pragma unroll
        for (int nt = 0; nt < 8; nt++) {
            int colb = nt * 8 + 2 * cq;
            uint32_t wr  = (colb < 32) ? mw0 : mw1;
            uint32_t wr8 = (colb < 32) ? nw0 : nw1;
            int sh = colb & 31;
            sc[nt][0] = ((wr  >> sh)       & 1) ? sc[nt][0] : -1e9f;
            sc[nt][1] = ((wr  >> (sh + 1)) & 1) ? sc[nt][1] : -1e9f;
            sc[nt][2] = ((wr8 >> sh)       & 1) ? sc[nt][2] : -1e9f;
            sc[nt][3] = ((wr8 >> (sh + 1)) & 1) ? sc[nt][3] : -1e9f;
        }

        float mx0 = -1e30f, mx1 = -1e30f;
        #pragma unroll
        for (int nt = 0; nt < 8; nt++) {
            mx0 = fmaxf(mx0, fmaxf(sc[nt][0], sc[nt][1]));
            mx1 = fmaxf(mx1, fmaxf(sc[nt][2], sc[nt][3]));
        }
        mx0 = fmaxf(mx0, __shfl_xor_sync(0xffffffffu, mx0, 1));
        mx0 = fmaxf(mx0, __shfl_xor_sync(0xffffffffu, mx0, 2));
        mx1 = fmaxf(mx1, __shfl_xor_sync(0xffffffffu, mx1, 1));
        mx1 = fmaxf(mx1, __shfl_xor_sync(0xffffffffu, mx1, 2));

        float mn0 = fmaxf(m0r, mx0), mn1 = fmaxf(m1r, mx1);
        float f0 = __expf(m0r - mn0), f1 = __expf(m1r - mn1);
        m0r = mn0; m1r = mn1;

        float s0 = 0.f, s1 = 0.f;
        #pragma unroll
        for (int nt = 0; nt < 8; nt++) {
            sc[nt][0] = __expf(sc[nt][0] - mn0);
            sc[nt][1] = __expf(sc[nt][1] - mn0);
            sc[nt][2] = __expf(sc[nt][2] - mn1);
            sc[nt][3] = __expf(sc[nt][3] - mn1);
            s0 += sc[nt][0] + sc[nt][1];
            s1 += sc[nt][2] + sc[nt][3];
        }
        s0 += __shfl_xor_sync(0xffffffffu, s0, 1);
        s0 += __shfl_xor_sync(0xffffffffu, s0, 2);
        s1 += __shfl_xor_sync(0xffffffffu, s1, 1);
        s1 += __shfl_xor_sync(0xffffffffu, s1, 2);
        l0 = l0 * f0 + s0;
        l1 = l1 * f1 + s1;

        #pragma unroll
        for (int nt = 0; nt < 8; nt++) {
            acc_o[nt][0] *= f0; acc_o[nt][1] *= f0;
            acc_o[nt][2] *= f1; acc_o[nt][3] *= f1;
        }

        uint32_t ph[4][4];
        #pragma unroll
        for (int j = 0; j < 4; j++) {
            ph[j][0] = h2u(sc[2*j  ][0], sc[2*j  ][1]);
            ph[j][1] = h2u(sc[2*j  ][2], sc[2*j  ][3]);
            ph[j][2] = h2u(sc[2*j+1][0], sc[2*j+1][1]);
            ph[j][3] = h2u(sc[2*j+1][2], sc[2*j+1][3]);
        }
        #pragma unroll
        for (int j = 0; j < 4; j++) {
            #pragma unroll
            for (int nn = 0; nn < 4; nn++) {
                uint32_t b0, b1, b2, b3;
                ldm_x4_t(b0, b1, b2, b3,
                         stV + (j * 16 + vRow) * FPIT + nn * 32 + vColB);
                mma16816(acc_o[nn * 2 + 0], ph[j], b0, b1);
                mma16816(acc_o[nn * 2 + 1], ph[j], b2, b3);
            }
        }

        __syncthreads();
        if (t + 2 < 16) loadKV(t + 2, s);
        CP_COMMIT();
    }

    float i0 = 1.f / l0, i1 = 1.f / l1;
    __half* Op = Og + ((size_t)b * Sx + q0 + wid * 16) * Dx + h * HDx;
    #pragma unroll
    for (int nt = 0; nt < 8; nt++) {
        int col = nt * 8 + 2 * cq;
        *(uint32_t*)&Op[(size_t)r * Dx + col] =
            h2u(acc_o[nt][0] * i0, acc_o[nt][1] * i0);
        *(uint32_t*)&Op[(size_t)(r + 8) * Dx + col] =
            h2u(acc_o[nt][2] * i1, acc_o[nt][3] * i1);
    }
}

// ---------------- mask bit-packing ------------------------------------------
__global__ __launch_bounds__(256)
void pack_mask(const int* __restrict__ mask, uint32_t* __restrict__ pk)
{
    int warp = blockIdx.x * 8 + (threadIdx.x >> 5);
    int lane = threadIdx.x & 31;
    const int* rowp = mask + (size_t)warp * 1024;
    uint32_t*  outp = pk   + (size_t)warp * 32;
    #pragma unroll
    for (int w = 0; w < 32; w++) {
        int v = rowp[w * 32 + lane];
        uint32_t word = __ballot_sync(0xffffffffu, v != 0);
        if (lane == 0) outp[w] = word;
    }
}

// ---------------- fp32 -> fp16 strided copy (row-major, no transpose) -------
// out[row*ldo + c] = (half)in[row*cols + c]; grid.y = rows
__global__ __launch_bounds__(256)
void conv_str(const float* __restrict__ in, __half* __restrict__ out,
              int cols, int ldo)
{
    int c4 = (blockIdx.x * 256 + threadIdx.x) * 4;
    int row = blockIdx.y;
    if (c4 < cols) {
        float4 v = *(const float4*)&in[(size_t)row * cols + c4];
        *(uint32_t*)&out[(size_t)row * ldo + c4]     = h2u(v.x, v.y);
        *(uint32_t*)&out[(size_t)row * ldo + c4 + 2] = h2u(v.z, v.w);
    }
}

// ---------------- fp32 -> fp16 elementwise ----------------------------------
__global__ __launch_bounds__(256)
void conv_h(const float* __restrict__ in, __half* __restrict__ out, int n2)
{
    int i = blockIdx.x * 256 + threadIdx.x;
    if (i < n2) {
        float2 v = *(const float2*)&in[i * 2];
        *(uint32_t*)&out[i * 2] = h2u(v.x, v.y);
    }
}

// ---------------- residual add + LayerNorm over 768 -------------------------
template<bool WH>
__global__ __launch_bounds__(192)
void ln_kernel(const float* __restrict__ a, const float* __restrict__ r,
               const float* __restrict__ g, const float* __restrict__ be,
               float* __restrict__ out, __half* __restrict__ outh)
{
    const int tid = threadIdx.x;
    const size_t base = (size_t)blockIdx.x * Dx + tid * 4;

    float4 xa = *(const float4*)&a[base];
    float4 xr = *(const float4*)&r[base];
    float x0 = xa.x + xr.x, x1 = xa.y + xr.y, x2 = xa.z + xr.z, x3 = xa.w + xr.w;

    float s = x0 + x1 + x2 + x3;
    float q = x0*x0 + x1*x1 + x2*x2 + x3*x3;
    #pragma unroll
    for (int o = 16; o; o >>= 1) {
        s += __shfl_xor_sync(0xffffffffu, s, o);
        q += __shfl_xor_sync(0xffffffffu, q, o);
    }
    __shared__ float ss[6], qq[6];
    if ((tid & 31) == 0) { ss[tid >> 5] = s; qq[tid >> 5] = q; }
    __syncthreads();
    if (tid == 0) {
        float S = 0.f, Qq = 0.f;
        #pragma unroll
        for (int w = 0; w < 6; w++) { S += ss[w]; Qq += qq[w]; }
        float mean = S * (1.f / Dx);
        float var  = Qq * (1.f / Dx) - mean * mean;
        ss[0] = mean;
        qq[0] = rsqrtf(var + EPSx);
    }
    __syncthreads();
    float mean = ss[0], rstd = qq[0];

    float4 gv = *(const float4*)&g[tid * 4];
    float4 bv = *(const float4*)&be[tid * 4];
    float4 o4;
    o4.x = (x0 - mean) * rstd * gv.x + bv.x;
    o4.y = (x1 - mean) * rstd * gv.y + bv.y;
    o4.z = (x2 - mean) * rstd * gv.z + bv.z;
    o4.w = (x3 - mean) * rstd * gv.w + bv.w;
    *(float4*)&out[base] = o4;
    if (WH) {
        *(uint32_t*)&outh[base]     = h2u(o4.x, o4.y);
        *(uint32_t*)&outh[base + 2] = h2u(o4.z, o4.w);
    }
}

// ---------------- launch ----------------------------------------------------
extern "C" void kernel_launch(void* const* d_in, const int* in_sizes, int n_in,
                              void* d_out, int out_size)
{
    const float* x    = (const float*)d_in[0];
    const int*   mask = (const int*)  d_in[1];
    const float* WQ   = (const float*)d_in[2];
    const float* WK   = (const float*)d_in[3];
    const float* WV   = (const float*)d_in[4];
    const float* Wfc  = (const float*)d_in[5];
    const float* W1   = (const float*)d_in[6];
    const float* b1   = (const float*)d_in[7];
    const float* W2   = (const float*)d_in[8];
    const float* b2   = (const float*)d_in[9];
    const float* g1   = (const float*)d_in[10];
    const float* be1  = (const float*)d_in[11];
    const float* g2   = (const float*)d_in[12];
    const float* be2  = (const float*)d_in[13];
    float* out = (float*)d_out;

    __half *xh, *QKVh, *atth, *nah, *lin1h;
    __half *Wqkv, *Wfch, *W1h, *W2h;
    float *proj, *na, *lin2;
    uint32_t* mpk;
    cudaGetSymbolAddress((void**)&xh,     g_xh);
    cudaGetSymbolAddress((void**)&QKVh,   g_QKVh);
    cudaGetSymbolAddress((void**)&mpk,    g_mpk);
    cudaGetSymbolAddress((void**)&atth,   g_atth);
    cudaGetSymbolAddress((void**)&proj,   g_proj);
    cudaGetSymbolAddress((void**)&na,     g_na);
    cudaGetSymbolAddress((void**)&nah,    g_nah);
    cudaGetSymbolAddress((void**)&lin1h,  g_lin1h);
    cudaGetSymbolAddress((void**)&lin2,   g_lin2);
    cudaGetSymbolAddress((void**)&Wqkv,   g_Wqkv);
    cudaGetSymbolAddress((void**)&Wfch,   g_Wfch);
    cudaGetSymbolAddress((void**)&W1h,    g_W1h);
    cudaGetSymbolAddress((void**)&W2h,    g_W2h);

    constexpr int SM128 = STAGES * (128 * PITCH + 32 * PITCHB);   // 75776
    cudaFuncSetAttribute(hgemm<128,0>, cudaFuncAttributeMaxDynamicSharedMemorySize, SM128);
    cudaFuncSetAttribute(hgemm<128,2>, cudaFuncAttributeMaxDynamicSharedMemorySize, SM128);
    cudaFuncSetAttribute(hgemm<128,3>, cudaFuncAttributeMaxDynamicSharedMemorySize, SM128);
    cudaFuncSetAttribute(hgemm<128,7>, cudaFuncAttributeMaxDynamicSharedMemorySize, SM128);
    cudaFuncSetAttribute(flash_kernel, cudaFuncAttributeMaxDynamicSharedMemorySize, FSMEM);

    // conversions (all row-major, no transposes) + mask packing
    conv_h<<<(Mx*Dx/2 + 255)/256, 256>>>(x, xh, Mx*Dx/2);
    pack_mask<<<Mx/8, 256>>>(mask, mpk);
    conv_str<<<dim3(Dx/1024 + 1, Dx),  256>>>(WQ,  Wqkv,          Dx,  3*Dx);
    conv_str<<<dim3(Dx/1024 + 1, Dx),  256>>>(WK,  Wqkv + Dx,     Dx,  3*Dx);
    conv_str<<<dim3(Dx/1024 + 1, Dx),  256>>>(WV,  Wqkv + 2*Dx,   Dx,  3*Dx);
    conv_str<<<dim3(Dx/1024 + 1, Dx),  256>>>(Wfc, Wfch,          Dx,  Dx);
    conv_str<<<dim3(FCx/1024, Dx),     256>>>(W1,  W1h,           FCx, FCx);
    conv_str<<<dim3(Dx/1024 + 1, FCx), 256>>>(W2,  W2h,           Dx,  Dx);

    // fused QKV projection (M=4096, N=2304, K=768), B row-major [768][2304]
    hgemm<128,7><<<dim3(3*Dx/128, Mx/128), 256, SM128>>>(xh, Wqkv, nullptr, QKVh,
                                                         Dx, Dx, 3*Dx, Dx);

    // fused attention
    __half* Qh = QKVh;
    __half* Kh = QKVh + (size_t)Mx * Dx;
    __half* Vh = QKVh + (size_t)2 * Mx * Dx;
    flash_kernel<<<dim3(Sx/128, Bx*Hx), 256, FSMEM>>>(Qh, Kh, Vh, mpk, atth);

    // output projection + LN1
    hgemm<128,0><<<dim3(Dx/128, Mx/128), 256, SM128>>>(atth, Wfch, nullptr, proj,
                                                       Dx, Dx, Dx, Dx);
    ln_kernel<true><<<Mx, 192>>>(proj, x, g1, be1, na, nah);

    // MLP + LN2
    hgemm<128,3><<<dim3(FCx/128, Mx/128), 256, SM128>>>(nah,   W1h, b1, lin1h,
                                                        Dx,  Dx,  FCx, FCx);
    hgemm<128,2><<<dim3(Dx/128,  Mx/128), 256, SM128>>>(lin1h, W2h, b2, lin2,
                                                        FCx, FCx, Dx,  Dx);
    ln_kernel<false><<<Mx, 192>>>(lin2, na, g2, be2, out, nullptr);
}